// round 1
// baseline (speedup 1.0000x reference)
#include <cuda_runtime.h>
#include <cstdint>
#include <cstddef>

#define D 128
#define HID 384
#define MAXN 100000
#define MAXE 500000
#define MAXG 5000

// ---------------------------------------------------------------------------
// Scratch layout (floats), one big static device buffer.
//   Zb  [E,384]  bond hidden
//   Ph  [N,384]  h @ bW1[0:128,:]
//   U1  [G,384]  u @ bW1[256:384,:] + bb1
//   Xa  [N,384]  atom MLP input
//   Za  [N,384]  atom hidden
//   Xg  [G,384]  global MLP input
//   Zg  [G,384]  global hidden
//   SH  [N,128]  segment_sum(h[src], dst)
//   SE  [N,128]  segment_sum(e_new, dst)
//   UH  [G,128]  segment_sum(h_new, graph_id)
//   UE  [G,128]  0.5 * segment_sum(SE, graph_id)
//   stats: sum[384], sq[384], scale[384], shift[384]
// ---------------------------------------------------------------------------
static const size_t OFF_ZB = 0;
static const size_t OFF_PH = OFF_ZB + (size_t)MAXE * HID;
static const size_t OFF_U1 = OFF_PH + (size_t)MAXN * HID;
static const size_t OFF_XA = OFF_U1 + (size_t)MAXG * HID;
static const size_t OFF_ZA = OFF_XA + (size_t)MAXN * HID;
static const size_t OFF_XG = OFF_ZA + (size_t)MAXN * HID;
static const size_t OFF_ZG = OFF_XG + (size_t)MAXG * HID;
static const size_t OFF_SH = OFF_ZG + (size_t)MAXG * HID;
static const size_t OFF_SE = OFF_SH + (size_t)MAXN * D;
static const size_t OFF_UH = OFF_SE + (size_t)MAXN * D;
static const size_t OFF_UE = OFF_UH + (size_t)MAXG * D;
static const size_t OFF_ST = OFF_UE + (size_t)MAXG * D;
static const size_t TOTAL_SCRATCH = OFF_ST + 4 * HID;

__device__ float g_scratch[TOTAL_SCRATCH];

// ---------------------------------------------------------------------------
// Zero kernel (grid-stride)
// ---------------------------------------------------------------------------
__global__ void zerok(float* __restrict__ p, size_t n) {
    size_t i = (size_t)blockIdx.x * blockDim.x + threadIdx.x;
    size_t st = (size_t)gridDim.x * blockDim.x;
    for (; i < n; i += st) p[i] = 0.f;
}

// ---------------------------------------------------------------------------
// SGEMM: C[M,Nd] = op(A)[M,K] @ B[K,Nd] (+bias per col)
//   BNA:  A element transformed as relu(a*scale[k]+shift[k])  (BatchNorm+ReLU)
//   SCAT: epilogue also atomicAdds each output row into segout[seg[row]*Nd+col]
// 128x128 tile, BK=8, 256 threads, 8x8 per thread.
// Requires: Nd % 128 == 0, K % 8 == 0 (only M may be ragged).
// ---------------------------------------------------------------------------
template<bool BNA, bool SCAT>
__global__ void __launch_bounds__(256, 2)
sgemm(const float* __restrict__ A, const float* __restrict__ B,
      const float* __restrict__ bias, float* __restrict__ C,
      int M, int K, int Nd,
      const float* __restrict__ bnscale, const float* __restrict__ bnshift,
      const int* __restrict__ seg, float* __restrict__ segout)
{
    __shared__ float As[8][128];
    __shared__ float Bs[8][128];
    __shared__ float ssc[HID];
    __shared__ float ssh[HID];

    const int tid = threadIdx.x;
    const int row0 = blockIdx.y * 128;
    const int col0 = blockIdx.x * 128;

    if (BNA) {
        for (int i = tid; i < K; i += 256) { ssc[i] = bnscale[i]; ssh[i] = bnshift[i]; }
    }
    __syncthreads();

    const int tr = tid >> 4;        // 0..15
    const int tc = tid & 15;        // 0..15
    const int aRow = tid >> 1;      // 0..127
    const int aC   = (tid & 1) << 2;
    const int bRow = tid >> 5;      // 0..7
    const int bC   = (tid & 31) << 2;

    float acc[8][8];
    #pragma unroll
    for (int i = 0; i < 8; i++)
        #pragma unroll
        for (int j = 0; j < 8; j++) acc[i][j] = 0.f;

    const bool aValid = (row0 + aRow) < M;
    const float* Aptr = A + (size_t)(row0 + aRow) * K + aC;
    const float* Bptr = B + (size_t)bRow * Nd + col0 + bC;

    for (int kt = 0; kt < K; kt += 8) {
        float4 av = make_float4(0.f, 0.f, 0.f, 0.f);
        if (aValid) av = *(const float4*)(Aptr + kt);
        float4 bv = *(const float4*)(Bptr + (size_t)kt * Nd);
        if (BNA) {
            const int kb = kt + aC;
            av.x = fmaxf(fmaf(av.x, ssc[kb + 0], ssh[kb + 0]), 0.f);
            av.y = fmaxf(fmaf(av.y, ssc[kb + 1], ssh[kb + 1]), 0.f);
            av.z = fmaxf(fmaf(av.z, ssc[kb + 2], ssh[kb + 2]), 0.f);
            av.w = fmaxf(fmaf(av.w, ssc[kb + 3], ssh[kb + 3]), 0.f);
        }
        __syncthreads();
        As[aC + 0][aRow] = av.x;
        As[aC + 1][aRow] = av.y;
        As[aC + 2][aRow] = av.z;
        As[aC + 3][aRow] = av.w;
        *(float4*)&Bs[bRow][bC] = bv;
        __syncthreads();
        #pragma unroll
        for (int k = 0; k < 8; k++) {
            float rm[8], rn[8];
            *(float4*)&rm[0] = *(const float4*)&As[k][tr * 8];
            *(float4*)&rm[4] = *(const float4*)&As[k][tr * 8 + 4];
            *(float4*)&rn[0] = *(const float4*)&Bs[k][tc * 8];
            *(float4*)&rn[4] = *(const float4*)&Bs[k][tc * 8 + 4];
            #pragma unroll
            for (int i = 0; i < 8; i++)
                #pragma unroll
                for (int j = 0; j < 8; j++)
                    acc[i][j] = fmaf(rm[i], rn[j], acc[i][j]);
        }
    }

    float bcol[8];
    #pragma unroll
    for (int j = 0; j < 8; j++)
        bcol[j] = bias ? bias[col0 + tc * 8 + j] : 0.f;

    #pragma unroll
    for (int i = 0; i < 8; i++) {
        const int r = row0 + tr * 8 + i;
        if (r < M) {
            float vals[8];
            #pragma unroll
            for (int j = 0; j < 8; j++) vals[j] = acc[i][j] + bcol[j];
            float* cr = C + (size_t)r * Nd + col0 + tc * 8;
            *(float4*)(cr)     = *(float4*)&vals[0];
            *(float4*)(cr + 4) = *(float4*)&vals[4];
            if (SCAT) {
                const int s = seg[r];
                float* so = segout + (size_t)s * Nd + col0 + tc * 8;
                #pragma unroll
                for (int j = 0; j < 8; j++) atomicAdd(so + j, vals[j]);
            }
        }
    }
}

// ---------------------------------------------------------------------------
// SH[dst] += h[src]  (float4 granularity)
// ---------------------------------------------------------------------------
__global__ void edge_scatter_h(const float* __restrict__ h, const int* __restrict__ src,
                               const int* __restrict__ dst, float* __restrict__ SH, int E)
{
    int idx = blockIdx.x * blockDim.x + threadIdx.x;
    int tot = E * 32;
    if (idx >= tot) return;
    int ei = idx >> 5;
    int c  = (idx & 31) << 2;
    int s = src[ei], d = dst[ei];
    float4 v = *(const float4*)&h[(size_t)s * D + c];
    float* o = SH + (size_t)d * D + c;
    atomicAdd(o + 0, v.x); atomicAdd(o + 1, v.y);
    atomicAdd(o + 2, v.z); atomicAdd(o + 3, v.w);
}

// ---------------------------------------------------------------------------
// Zb[e] += Ph[src] + Ph[dst] + U1[graph_id[src]]; accumulate column stats.
// One block = 384 threads (one per hidden column), grid-stride over rows.
// ---------------------------------------------------------------------------
__global__ void finalize_bond(float* __restrict__ Zb, const float* __restrict__ Ph,
                              const float* __restrict__ U1,
                              const int* __restrict__ src, const int* __restrict__ dst,
                              const int* __restrict__ gid,
                              float* __restrict__ sum, float* __restrict__ sq, int E)
{
    const int c = threadIdx.x;
    float s = 0.f, q = 0.f;
    for (int r = blockIdx.x; r < E; r += gridDim.x) {
        const int si = src[r];
        const int di = dst[r];
        const int g  = gid[si];
        const size_t base = (size_t)r * HID + c;
        float v = Zb[base] + Ph[(size_t)si * HID + c] + Ph[(size_t)di * HID + c]
                + U1[(size_t)g * HID + c];
        Zb[base] = v;
        s += v; q += v * v;
    }
    atomicAdd(&sum[c], s);
    atomicAdd(&sq[c], q);
}

// ---------------------------------------------------------------------------
// Column stats over Z[M,384]
// ---------------------------------------------------------------------------
__global__ void colstats(const float* __restrict__ Z, float* __restrict__ sum,
                         float* __restrict__ sq, int M)
{
    const int c = threadIdx.x;
    float s = 0.f, q = 0.f;
    for (int r = blockIdx.x; r < M; r += gridDim.x) {
        float v = Z[(size_t)r * HID + c];
        s += v; q += v * v;
    }
    atomicAdd(&sum[c], s);
    atomicAdd(&sq[c], q);
}

// ---------------------------------------------------------------------------
// BN scale/shift from stats; clears stats for the next use.
// ---------------------------------------------------------------------------
__global__ void bn_prep(float* __restrict__ sum, float* __restrict__ sq,
                        const float* __restrict__ g1, const float* __restrict__ beta1,
                        float* __restrict__ scale, float* __restrict__ shift, float invM)
{
    const int c = threadIdx.x;
    float mean = sum[c] * invM;
    float var  = sq[c] * invM - mean * mean;
    float rstd = rsqrtf(var + 1e-5f);
    float sc = rstd * g1[c];
    scale[c] = sc;
    shift[c] = beta1[c] - mean * sc;
    sum[c] = 0.f;
    sq[c] = 0.f;
}

// ---------------------------------------------------------------------------
// Xa[n] = [SH[n]+h[n], SE[n], u[gid[n]]]; also UE[gid[n]] += 0.5*SE[n]
// ---------------------------------------------------------------------------
__global__ void node_build(const float* __restrict__ h, const float* __restrict__ u,
                           const int* __restrict__ gid,
                           const float* __restrict__ SH, const float* __restrict__ SE,
                           float* __restrict__ Xa, float* __restrict__ UE, int N)
{
    int idx = blockIdx.x * blockDim.x + threadIdx.x;
    int tot = N * 32;
    if (idx >= tot) return;
    int n = idx >> 5;
    int c = (idx & 31) << 2;
    int g = gid[n];
    float4 sh = *(const float4*)&SH[(size_t)n * D + c];
    float4 hv = *(const float4*)&h[(size_t)n * D + c];
    float4 se = *(const float4*)&SE[(size_t)n * D + c];
    float4 uv = *(const float4*)&u[(size_t)g * D + c];
    size_t base = (size_t)n * HID;
    *(float4*)&Xa[base + c]         = make_float4(sh.x + hv.x, sh.y + hv.y, sh.z + hv.z, sh.w + hv.w);
    *(float4*)&Xa[base + D + c]     = se;
    *(float4*)&Xa[base + 2 * D + c] = uv;
    float* o = UE + (size_t)g * D + c;
    atomicAdd(o + 0, 0.5f * se.x); atomicAdd(o + 1, 0.5f * se.y);
    atomicAdd(o + 2, 0.5f * se.z); atomicAdd(o + 3, 0.5f * se.w);
}

// ---------------------------------------------------------------------------
// Xg[g] = [UH[g], UE[g], u[g]]
// ---------------------------------------------------------------------------
__global__ void graph_build(const float* __restrict__ u, const float* __restrict__ UH,
                            const float* __restrict__ UE, float* __restrict__ Xg, int G)
{
    int idx = blockIdx.x * blockDim.x + threadIdx.x;
    int tot = G * 32;
    if (idx >= tot) return;
    int g = idx >> 5;
    int c = (idx & 31) << 2;
    size_t base = (size_t)g * HID;
    *(float4*)&Xg[base + c]         = *(const float4*)&UH[(size_t)g * D + c];
    *(float4*)&Xg[base + D + c]     = *(const float4*)&UE[(size_t)g * D + c];
    *(float4*)&Xg[base + 2 * D + c] = *(const float4*)&u[(size_t)g * D + c];
}

// ---------------------------------------------------------------------------
// GEMM dispatch helper
// ---------------------------------------------------------------------------
static void run_gemm(bool bnA, bool scat,
                     const float* A, const float* B, const float* bias, float* C,
                     int M, int K, int Nd,
                     const float* sc, const float* sh,
                     const int* seg, float* segout)
{
    dim3 grid(Nd / 128, (M + 127) / 128);
    if (bnA) {
        if (scat) sgemm<true,  true ><<<grid, 256>>>(A, B, bias, C, M, K, Nd, sc, sh, seg, segout);
        else      sgemm<true,  false><<<grid, 256>>>(A, B, bias, C, M, K, Nd, sc, sh, seg, segout);
    } else {
        if (scat) sgemm<false, true ><<<grid, 256>>>(A, B, bias, C, M, K, Nd, sc, sh, seg, segout);
        else      sgemm<false, false><<<grid, 256>>>(A, B, bias, C, M, K, Nd, sc, sh, seg, segout);
    }
}

extern "C" void kernel_launch(void* const* d_in, const int* in_sizes, int n_in,
                              void* d_out, int out_size)
{
    const float* h   = (const float*)d_in[0];
    const float* e   = (const float*)d_in[1];
    const float* u   = (const float*)d_in[2];
    const int*   src = (const int*)d_in[3];
    const int*   dst = (const int*)d_in[4];
    const int*   gid = (const int*)d_in[5];

    const float* bW1 = (const float*)d_in[6];
    const float* bb1 = (const float*)d_in[7];
    const float* bg1 = (const float*)d_in[8];
    const float* bbt = (const float*)d_in[9];
    const float* bW2 = (const float*)d_in[10];
    const float* bb2 = (const float*)d_in[11];

    const float* aW1 = (const float*)d_in[12];
    const float* ab1 = (const float*)d_in[13];
    const float* ag1 = (const float*)d_in[14];
    const float* abt = (const float*)d_in[15];
    const float* aW2 = (const float*)d_in[16];
    const float* ab2 = (const float*)d_in[17];

    const float* gW1 = (const float*)d_in[18];
    const float* gb1 = (const float*)d_in[19];
    const float* gg1 = (const float*)d_in[20];
    const float* gbt = (const float*)d_in[21];
    const float* gW2 = (const float*)d_in[22];
    const float* gb2 = (const float*)d_in[23];

    const int N = in_sizes[5];
    const int E = in_sizes[3];
    const int G = in_sizes[2] / D;

    float* scratch = nullptr;
    cudaGetSymbolAddress((void**)&scratch, g_scratch);

    float* Zb = scratch + OFF_ZB;
    float* Ph = scratch + OFF_PH;
    float* U1 = scratch + OFF_U1;
    float* Xa = scratch + OFF_XA;
    float* Za = scratch + OFF_ZA;
    float* Xg = scratch + OFF_XG;
    float* Zg = scratch + OFF_ZG;
    float* SH = scratch + OFF_SH;
    float* SE = scratch + OFF_SE;
    float* UH = scratch + OFF_UH;
    float* UE = scratch + OFF_UE;
    float* st_sum   = scratch + OFF_ST;
    float* st_sq    = st_sum + HID;
    float* bn_scale = st_sq + HID;
    float* bn_shift = bn_scale + HID;

    float* out_h = (float*)d_out;
    float* out_e = out_h + (size_t)N * D;
    float* out_u = out_e + (size_t)E * D;

    // Zero accumulators (SH, SE, UH, UE, stats) — contiguous region.
    {
        size_t nz = (size_t)MAXN * D * 2 + (size_t)MAXG * D * 2 + 2 * HID;
        zerok<<<2048, 256>>>(SH, nz);
    }

    // ---- Bond path ----
    // Ph = h @ bW1[0:D,:]
    run_gemm(false, false, h, bW1, nullptr, Ph, N, D, HID, nullptr, nullptr, nullptr, nullptr);
    // U1 = u @ bW1[2D:3D,:] + bb1   (bias folded here)
    run_gemm(false, false, u, bW1 + (size_t)2 * D * HID, bb1, U1, G, D, HID, nullptr, nullptr, nullptr, nullptr);
    // Zb = e @ bW1[D:2D,:]
    run_gemm(false, false, e, bW1 + (size_t)D * HID, nullptr, Zb, E, D, HID, nullptr, nullptr, nullptr, nullptr);
    // SH[dst] += h[src]
    edge_scatter_h<<<(E * 32 + 255) / 256, 256>>>(h, src, dst, SH, E);
    // Zb += Ph[src] + Ph[dst] + U1[gid[src]]; column stats
    finalize_bond<<<2048, HID>>>(Zb, Ph, U1, src, dst, gid, st_sum, st_sq, E);
    bn_prep<<<1, HID>>>(st_sum, st_sq, bg1, bbt, bn_scale, bn_shift, 1.f / (float)E);
    // e_new = relu(BN(Zb)) @ bW2 + bb2 ; SE[dst] += e_new
    run_gemm(true, true, Zb, bW2, bb2, out_e, E, HID, D, bn_scale, bn_shift, dst, SE);

    // ---- Atom path ----
    node_build<<<(N * 32 + 255) / 256, 256>>>(h, u, gid, SH, SE, Xa, UE, N);
    run_gemm(false, false, Xa, aW1, ab1, Za, N, HID, HID, nullptr, nullptr, nullptr, nullptr);
    colstats<<<1024, HID>>>(Za, st_sum, st_sq, N);
    bn_prep<<<1, HID>>>(st_sum, st_sq, ag1, abt, bn_scale, bn_shift, 1.f / (float)N);
    // h_new = relu(BN(Za)) @ aW2 + ab2 ; UH[gid] += h_new
    run_gemm(true, true, Za, aW2, ab2, out_h, N, HID, D, bn_scale, bn_shift, gid, UH);

    // ---- Global path ----
    graph_build<<<(G * 32 + 255) / 256, 256>>>(u, UH, UE, Xg, G);
    run_gemm(false, false, Xg, gW1, gb1, Zg, G, HID, HID, nullptr, nullptr, nullptr, nullptr);
    colstats<<<64, HID>>>(Zg, st_sum, st_sq, G);
    bn_prep<<<1, HID>>>(st_sum, st_sq, gg1, gbt, bn_scale, bn_shift, 1.f / (float)G);
    run_gemm(true, false, Zg, gW2, gb2, out_u, G, HID, D, bn_scale, bn_shift, nullptr, nullptr);
}

// round 2
// speedup vs baseline: 1.2362x; 1.2362x over previous
#include <cuda_runtime.h>
#include <cstdint>
#include <cstddef>

#define D 128
#define HID 384
#define MAXN 100000
#define MAXE 500000
#define MAXG 5000

// ---------------------------------------------------------------------------
// Scratch layout (floats)
// ---------------------------------------------------------------------------
static const size_t OFF_ZB = 0;
static const size_t OFF_PH = OFF_ZB + (size_t)MAXE * HID;
static const size_t OFF_U1 = OFF_PH + (size_t)MAXN * HID;
static const size_t OFF_XA = OFF_U1 + (size_t)MAXG * HID;
static const size_t OFF_ZA = OFF_XA + (size_t)MAXN * HID;
static const size_t OFF_XG = OFF_ZA + (size_t)MAXN * HID;
static const size_t OFF_ZG = OFF_XG + (size_t)MAXG * HID;
static const size_t OFF_SH = OFF_ZG + (size_t)MAXG * HID;
static const size_t OFF_SE = OFF_SH + (size_t)MAXN * D;
static const size_t OFF_UH = OFF_SE + (size_t)MAXN * D;
static const size_t OFF_UE = OFF_UH + (size_t)MAXG * D;
static const size_t OFF_ST = OFF_UE + (size_t)MAXG * D;
static const size_t TOTAL_SCRATCH = OFF_ST + 4 * HID;

__device__ float g_scratch[TOTAL_SCRATCH];

// ---------------------------------------------------------------------------
// Packed f32x2 helpers (FFMA2 — ptxas never emits this from C++, only PTX)
// ---------------------------------------------------------------------------
__device__ __forceinline__ unsigned long long f2fma(unsigned long long a,
                                                    unsigned long long b,
                                                    unsigned long long c) {
    unsigned long long d;
    asm("fma.rn.f32x2 %0, %1, %2, %3;" : "=l"(d) : "l"(a), "l"(b), "l"(c));
    return d;
}
__device__ __forceinline__ unsigned long long fdup(float x) {
    unsigned long long d;
    asm("mov.b64 %0, {%1, %1};" : "=l"(d) : "f"(x));
    return d;
}
__device__ __forceinline__ void f2unpack(unsigned long long v, float& lo, float& hi) {
    asm("mov.b64 {%0, %1}, %2;" : "=f"(lo), "=f"(hi) : "l"(v));
}

// ---------------------------------------------------------------------------
// Zero kernel
// ---------------------------------------------------------------------------
__global__ void zerok(float* __restrict__ p, size_t n) {
    size_t i = (size_t)blockIdx.x * blockDim.x + threadIdx.x;
    size_t st = (size_t)gridDim.x * blockDim.x;
    for (; i < n; i += st) p[i] = 0.f;
}

// ---------------------------------------------------------------------------
// SGEMM with packed f32x2 math.  C[M,Nd] = op(A)[M,K] @ B[K,Nd] (+bias)
//   BNA:   A transformed as relu(a*scale[k]+shift[k]) during staging
//   SCAT:  epilogue atomicAdds output rows into segout[seg[row]]
//   GATH:  epilogue adds Ph[src[r]] + Ph[dst[r]] + U1[gid[src[r]]] (bond fuse)
//   STATS: epilogue accumulates per-column sum / sum-of-squares
// 128x128 tile, BK=16, 256 threads, 8x8 per thread (packed as 8x4 f32x2).
// Requires Nd % 128 == 0, K % 16 == 0.
// ---------------------------------------------------------------------------
template<bool BNA, bool SCAT, bool GATH, bool STATS>
__global__ void __launch_bounds__(256, 2)
sgemm(const float* __restrict__ A, const float* __restrict__ B,
      const float* __restrict__ bias, float* __restrict__ C,
      int M, int K, int Nd,
      const float* __restrict__ bnscale, const float* __restrict__ bnshift,
      const int* __restrict__ seg, float* __restrict__ segout,
      const float* __restrict__ Ph, const float* __restrict__ U1,
      const int* __restrict__ src, const int* __restrict__ dst,
      const int* __restrict__ gid,
      float* __restrict__ st_sum, float* __restrict__ st_sq)
{
    __shared__ __align__(16) float As[16][128];
    __shared__ __align__(16) float Bs[16][128];
    __shared__ float ssc[HID];
    __shared__ float ssh[HID];

    const int tid = threadIdx.x;
    const int row0 = blockIdx.y * 128;
    const int col0 = blockIdx.x * 128;

    if (BNA) {
        for (int i = tid; i < K; i += 256) { ssc[i] = bnscale[i]; ssh[i] = bnshift[i]; }
        __syncthreads();
    }

    const int tr = tid >> 4;          // 0..15
    const int tc = tid & 15;          // 0..15
    const int aRow = tid >> 1;        // 0..127
    const int aC   = (tid & 1) << 3;  // 0 or 8
    const int bRow = tid >> 4;        // 0..15
    const int bC   = (tid & 15) << 3; // 0..120 step 8

    unsigned long long acc2[8][4];
    #pragma unroll
    for (int i = 0; i < 8; i++)
        #pragma unroll
        for (int j = 0; j < 4; j++) acc2[i][j] = 0ull;

    const bool aValid = (row0 + aRow) < M;
    const float* Aptr = A + (size_t)(row0 + aRow) * K + aC;
    const float* Bptr = B + (size_t)bRow * Nd + col0 + bC;

    for (int kt = 0; kt < K; kt += 16) {
        float av[8];
        if (aValid) {
            *(float4*)&av[0] = *(const float4*)(Aptr + kt);
            *(float4*)&av[4] = *(const float4*)(Aptr + kt + 4);
        } else {
            #pragma unroll
            for (int j = 0; j < 8; j++) av[j] = 0.f;
        }
        float bv[8];
        *(float4*)&bv[0] = *(const float4*)(Bptr + (size_t)kt * Nd);
        *(float4*)&bv[4] = *(const float4*)(Bptr + (size_t)kt * Nd + 4);
        if (BNA) {
            #pragma unroll
            for (int j = 0; j < 8; j++) {
                const int kb = kt + aC + j;
                av[j] = fmaxf(fmaf(av[j], ssc[kb], ssh[kb]), 0.f);
            }
        }
        __syncthreads();
        #pragma unroll
        for (int j = 0; j < 8; j++) As[aC + j][aRow] = av[j];
        *(float4*)&Bs[bRow][bC]     = *(float4*)&bv[0];
        *(float4*)&Bs[bRow][bC + 4] = *(float4*)&bv[4];
        __syncthreads();
        #pragma unroll
        for (int k = 0; k < 16; k++) {
            float rm[8];
            *(float4*)&rm[0] = *(const float4*)&As[k][tr * 8];
            *(float4*)&rm[4] = *(const float4*)&As[k][tr * 8 + 4];
            unsigned long long rn2[4];
            *(ulonglong2*)&rn2[0] = *(const ulonglong2*)&Bs[k][tc * 8];
            *(ulonglong2*)&rn2[2] = *(const ulonglong2*)&Bs[k][tc * 8 + 4];
            unsigned long long rm2[8];
            #pragma unroll
            for (int i = 0; i < 8; i++) rm2[i] = fdup(rm[i]);
            #pragma unroll
            for (int i = 0; i < 8; i++)
                #pragma unroll
                for (int j = 0; j < 4; j++)
                    acc2[i][j] = f2fma(rm2[i], rn2[j], acc2[i][j]);
        }
    }

    const int colbase = col0 + tc * 8;
    float bcol[8];
    #pragma unroll
    for (int j = 0; j < 8; j++)
        bcol[j] = bias ? bias[colbase + j] : 0.f;

    float cs[8], cq[8];
    if (STATS) {
        #pragma unroll
        for (int j = 0; j < 8; j++) { cs[j] = 0.f; cq[j] = 0.f; }
    }

    #pragma unroll
    for (int i = 0; i < 8; i++) {
        const int r = row0 + tr * 8 + i;
        if (r < M) {
            float vals[8];
            #pragma unroll
            for (int j = 0; j < 4; j++)
                f2unpack(acc2[i][j], vals[2 * j], vals[2 * j + 1]);
            #pragma unroll
            for (int j = 0; j < 8; j++) vals[j] += bcol[j];
            if (GATH) {
                const int si = src[r];
                const int di = dst[r];
                const int g  = gid[si];
                float ga[8], gb[8], gc[8];
                const float* p1 = Ph + (size_t)si * HID + colbase;
                const float* p2 = Ph + (size_t)di * HID + colbase;
                const float* p3 = U1 + (size_t)g  * HID + colbase;
                *(float4*)&ga[0] = *(const float4*)p1;       *(float4*)&ga[4] = *(const float4*)(p1 + 4);
                *(float4*)&gb[0] = *(const float4*)p2;       *(float4*)&gb[4] = *(const float4*)(p2 + 4);
                *(float4*)&gc[0] = *(const float4*)p3;       *(float4*)&gc[4] = *(const float4*)(p3 + 4);
                #pragma unroll
                for (int j = 0; j < 8; j++) vals[j] += ga[j] + gb[j] + gc[j];
            }
            float* cr = C + (size_t)r * Nd + colbase;
            *(float4*)(cr)     = *(float4*)&vals[0];
            *(float4*)(cr + 4) = *(float4*)&vals[4];
            if (SCAT) {
                const int s = seg[r];
                float* so = segout + (size_t)s * Nd + colbase;
                #pragma unroll
                for (int j = 0; j < 8; j++) atomicAdd(so + j, vals[j]);
            }
            if (STATS) {
                #pragma unroll
                for (int j = 0; j < 8; j++) { cs[j] += vals[j]; cq[j] += vals[j] * vals[j]; }
            }
        }
    }

    if (STATS) {
        __syncthreads();   // done with As/Bs as GEMM buffers; reuse for reduction
        #pragma unroll
        for (int j = 0; j < 8; j++) {
            As[tr][tc * 8 + j] = cs[j];
            Bs[tr][tc * 8 + j] = cq[j];
        }
        __syncthreads();
        if (tid < 128) {
            float s = 0.f, q = 0.f;
            #pragma unroll
            for (int t = 0; t < 16; t++) { s += As[t][tid]; q += Bs[t][tid]; }
            atomicAdd(&st_sum[col0 + tid], s);
            atomicAdd(&st_sq[col0 + tid], q);
        }
    }
}

// ---------------------------------------------------------------------------
// SH[dst] += h[src]
// ---------------------------------------------------------------------------
__global__ void edge_scatter_h(const float* __restrict__ h, const int* __restrict__ src,
                               const int* __restrict__ dst, float* __restrict__ SH, int E)
{
    int idx = blockIdx.x * blockDim.x + threadIdx.x;
    int tot = E * 32;
    if (idx >= tot) return;
    int ei = idx >> 5;
    int c  = (idx & 31) << 2;
    int s = src[ei], d = dst[ei];
    float4 v = *(const float4*)&h[(size_t)s * D + c];
    float* o = SH + (size_t)d * D + c;
    atomicAdd(o + 0, v.x); atomicAdd(o + 1, v.y);
    atomicAdd(o + 2, v.z); atomicAdd(o + 3, v.w);
}

// ---------------------------------------------------------------------------
// BN scale/shift; clears stats for next use.
// ---------------------------------------------------------------------------
__global__ void bn_prep(float* __restrict__ sum, float* __restrict__ sq,
                        const float* __restrict__ g1, const float* __restrict__ beta1,
                        float* __restrict__ scale, float* __restrict__ shift, float invM)
{
    const int c = threadIdx.x;
    float mean = sum[c] * invM;
    float var  = sq[c] * invM - mean * mean;
    float rstd = rsqrtf(var + 1e-5f);
    float sc = rstd * g1[c];
    scale[c] = sc;
    shift[c] = beta1[c] - mean * sc;
    sum[c] = 0.f;
    sq[c] = 0.f;
}

// ---------------------------------------------------------------------------
// Xa[n] = [SH[n]+h[n], SE[n], u[gid[n]]]; UE[gid[n]] += 0.5*SE[n]
// ---------------------------------------------------------------------------
__global__ void node_build(const float* __restrict__ h, const float* __restrict__ u,
                           const int* __restrict__ gid,
                           const float* __restrict__ SH, const float* __restrict__ SE,
                           float* __restrict__ Xa, float* __restrict__ UE, int N)
{
    int idx = blockIdx.x * blockDim.x + threadIdx.x;
    int tot = N * 32;
    if (idx >= tot) return;
    int n = idx >> 5;
    int c = (idx & 31) << 2;
    int g = gid[n];
    float4 sh = *(const float4*)&SH[(size_t)n * D + c];
    float4 hv = *(const float4*)&h[(size_t)n * D + c];
    float4 se = *(const float4*)&SE[(size_t)n * D + c];
    float4 uv = *(const float4*)&u[(size_t)g * D + c];
    size_t base = (size_t)n * HID;
    *(float4*)&Xa[base + c]         = make_float4(sh.x + hv.x, sh.y + hv.y, sh.z + hv.z, sh.w + hv.w);
    *(float4*)&Xa[base + D + c]     = se;
    *(float4*)&Xa[base + 2 * D + c] = uv;
    float* o = UE + (size_t)g * D + c;
    atomicAdd(o + 0, 0.5f * se.x); atomicAdd(o + 1, 0.5f * se.y);
    atomicAdd(o + 2, 0.5f * se.z); atomicAdd(o + 3, 0.5f * se.w);
}

// ---------------------------------------------------------------------------
// Xg[g] = [UH[g], UE[g], u[g]]
// ---------------------------------------------------------------------------
__global__ void graph_build(const float* __restrict__ u, const float* __restrict__ UH,
                            const float* __restrict__ UE, float* __restrict__ Xg, int G)
{
    int idx = blockIdx.x * blockDim.x + threadIdx.x;
    int tot = G * 32;
    if (idx >= tot) return;
    int g = idx >> 5;
    int c = (idx & 31) << 2;
    size_t base = (size_t)g * HID;
    *(float4*)&Xg[base + c]         = *(const float4*)&UH[(size_t)g * D + c];
    *(float4*)&Xg[base + D + c]     = *(const float4*)&UE[(size_t)g * D + c];
    *(float4*)&Xg[base + 2 * D + c] = *(const float4*)&u[(size_t)g * D + c];
}

// ---------------------------------------------------------------------------
// Dispatch helper (only the 5 used combos are instantiated)
// mode: 0 = plain, 1 = GATH+STATS, 2 = BNA+SCAT, 3 = STATS, 4 = BNA
// ---------------------------------------------------------------------------
static void run_gemm(int mode,
                     const float* A, const float* B, const float* bias, float* C,
                     int M, int K, int Nd,
                     const float* sc, const float* sh,
                     const int* seg, float* segout,
                     const float* Ph, const float* U1,
                     const int* src, const int* dst, const int* gid,
                     float* st_sum, float* st_sq)
{
    dim3 grid(Nd / 128, (M + 127) / 128);
    switch (mode) {
    case 0: sgemm<false,false,false,false><<<grid,256>>>(A,B,bias,C,M,K,Nd,sc,sh,seg,segout,Ph,U1,src,dst,gid,st_sum,st_sq); break;
    case 1: sgemm<false,false,true, true ><<<grid,256>>>(A,B,bias,C,M,K,Nd,sc,sh,seg,segout,Ph,U1,src,dst,gid,st_sum,st_sq); break;
    case 2: sgemm<true, true, false,false><<<grid,256>>>(A,B,bias,C,M,K,Nd,sc,sh,seg,segout,Ph,U1,src,dst,gid,st_sum,st_sq); break;
    case 3: sgemm<false,false,false,true ><<<grid,256>>>(A,B,bias,C,M,K,Nd,sc,sh,seg,segout,Ph,U1,src,dst,gid,st_sum,st_sq); break;
    case 4: sgemm<true, false,false,false><<<grid,256>>>(A,B,bias,C,M,K,Nd,sc,sh,seg,segout,Ph,U1,src,dst,gid,st_sum,st_sq); break;
    }
}

extern "C" void kernel_launch(void* const* d_in, const int* in_sizes, int n_in,
                              void* d_out, int out_size)
{
    const float* h   = (const float*)d_in[0];
    const float* e   = (const float*)d_in[1];
    const float* u   = (const float*)d_in[2];
    const int*   src = (const int*)d_in[3];
    const int*   dst = (const int*)d_in[4];
    const int*   gid = (const int*)d_in[5];

    const float* bW1 = (const float*)d_in[6];
    const float* bb1 = (const float*)d_in[7];
    const float* bg1 = (const float*)d_in[8];
    const float* bbt = (const float*)d_in[9];
    const float* bW2 = (const float*)d_in[10];
    const float* bb2 = (const float*)d_in[11];

    const float* aW1 = (const float*)d_in[12];
    const float* ab1 = (const float*)d_in[13];
    const float* ag1 = (const float*)d_in[14];
    const float* abt = (const float*)d_in[15];
    const float* aW2 = (const float*)d_in[16];
    const float* ab2 = (const float*)d_in[17];

    const float* gW1 = (const float*)d_in[18];
    const float* gb1 = (const float*)d_in[19];
    const float* gg1 = (const float*)d_in[20];
    const float* gbt = (const float*)d_in[21];
    const float* gW2 = (const float*)d_in[22];
    const float* gb2 = (const float*)d_in[23];

    const int N = in_sizes[5];
    const int E = in_sizes[3];
    const int G = in_sizes[2] / D;

    float* scratch = nullptr;
    cudaGetSymbolAddress((void**)&scratch, g_scratch);

    float* Zb = scratch + OFF_ZB;
    float* Ph = scratch + OFF_PH;
    float* U1 = scratch + OFF_U1;
    float* Xa = scratch + OFF_XA;
    float* Za = scratch + OFF_ZA;
    float* Xg = scratch + OFF_XG;
    float* Zg = scratch + OFF_ZG;
    float* SH = scratch + OFF_SH;
    float* SE = scratch + OFF_SE;
    float* UH = scratch + OFF_UH;
    float* UE = scratch + OFF_UE;
    float* st_sum   = scratch + OFF_ST;
    float* st_sq    = st_sum + HID;
    float* bn_scale = st_sq + HID;
    float* bn_shift = bn_scale + HID;

    float* out_h = (float*)d_out;
    float* out_e = out_h + (size_t)N * D;
    float* out_u = out_e + (size_t)E * D;

    // Zero accumulators (SH, SE, UH, UE, stats) — contiguous region.
    {
        size_t nz = (size_t)MAXN * D * 2 + (size_t)MAXG * D * 2 + 2 * HID;
        zerok<<<2048, 256>>>(SH, nz);
    }

    // ---- Bond path ----
    // Ph = h @ bW1[0:D,:]
    run_gemm(0, h, bW1, nullptr, Ph, N, D, HID,
             nullptr, nullptr, nullptr, nullptr, nullptr, nullptr, nullptr, nullptr, nullptr, nullptr, nullptr);
    // U1 = u @ bW1[2D:3D,:] + bb1
    run_gemm(0, u, bW1 + (size_t)2 * D * HID, bb1, U1, G, D, HID,
             nullptr, nullptr, nullptr, nullptr, nullptr, nullptr, nullptr, nullptr, nullptr, nullptr, nullptr);
    // SH[dst] += h[src]  (overlaps with GEMMs above on same stream order)
    edge_scatter_h<<<(E * 32 + 255) / 256, 256>>>(h, src, dst, SH, E);
    // Zb = e @ bW1[D:2D,:] + Ph[src] + Ph[dst] + U1[gid[src]]; fused column stats
    run_gemm(1, e, bW1 + (size_t)D * HID, nullptr, Zb, E, D, HID,
             nullptr, nullptr, nullptr, nullptr, Ph, U1, src, dst, gid, st_sum, st_sq);
    bn_prep<<<1, HID>>>(st_sum, st_sq, bg1, bbt, bn_scale, bn_shift, 1.f / (float)E);
    // e_new = relu(BN(Zb)) @ bW2 + bb2 ; SE[dst] += e_new
    run_gemm(2, Zb, bW2, bb2, out_e, E, HID, D,
             bn_scale, bn_shift, dst, SE, nullptr, nullptr, nullptr, nullptr, nullptr, nullptr, nullptr);

    // ---- Atom path ----
    node_build<<<(N * 32 + 255) / 256, 256>>>(h, u, gid, SH, SE, Xa, UE, N);
    // Za = Xa @ aW1 + ab1; fused stats
    run_gemm(3, Xa, aW1, ab1, Za, N, HID, HID,
             nullptr, nullptr, nullptr, nullptr, nullptr, nullptr, nullptr, nullptr, nullptr, st_sum, st_sq);
    bn_prep<<<1, HID>>>(st_sum, st_sq, ag1, abt, bn_scale, bn_shift, 1.f / (float)N);
    // h_new = relu(BN(Za)) @ aW2 + ab2 ; UH[gid] += h_new
    run_gemm(2, Za, aW2, ab2, out_h, N, HID, D,
             bn_scale, bn_shift, gid, UH, nullptr, nullptr, nullptr, nullptr, nullptr, nullptr, nullptr);

    // ---- Global path ----
    graph_build<<<(G * 32 + 255) / 256, 256>>>(u, UH, UE, Xg, G);
    run_gemm(3, Xg, gW1, gb1, Zg, G, HID, HID,
             nullptr, nullptr, nullptr, nullptr, nullptr, nullptr, nullptr, nullptr, nullptr, st_sum, st_sq);
    bn_prep<<<1, HID>>>(st_sum, st_sq, gg1, gbt, bn_scale, bn_shift, 1.f / (float)G);
    run_gemm(4, Zg, gW2, gb2, out_u, G, HID, D,
             bn_scale, bn_shift, nullptr, nullptr, nullptr, nullptr, nullptr, nullptr, nullptr, nullptr, nullptr);
}

// round 5
// speedup vs baseline: 1.2881x; 1.0421x over previous
#include <cuda_runtime.h>
#include <cuda_bf16.h>
#include <cstdint>
#include <cstddef>

#define D 128
#define HID 384
#define MAXN 100000
#define MAXE 500000
#define MAXG 5000

// ---------------------------------------------------------------------------
// Scratch layout (floats)
// ---------------------------------------------------------------------------
static const size_t OFF_ZB = 0;
static const size_t OFF_PH = OFF_ZB + (size_t)MAXE * HID;
static const size_t OFF_U1 = OFF_PH + (size_t)MAXN * HID;
static const size_t OFF_XA = OFF_U1 + (size_t)MAXG * HID;
static const size_t OFF_ZA = OFF_XA + (size_t)MAXN * HID;
static const size_t OFF_XG = OFF_ZA + (size_t)MAXN * HID;
static const size_t OFF_ZG = OFF_XG + (size_t)MAXG * HID;
static const size_t OFF_SH = OFF_ZG + (size_t)MAXG * HID;
static const size_t OFF_SE = OFF_SH + (size_t)MAXN * D;
static const size_t OFF_UH = OFF_SE + (size_t)MAXN * D;
static const size_t OFF_UE = OFF_UH + (size_t)MAXG * D;
static const size_t OFF_ST = OFF_UE + (size_t)MAXG * D;
static const size_t OFF_WP = OFF_ST + 4 * HID;   // prepped weights (bf16 hi then lo per weight)
static const size_t WP_FLOATS = 589824;          // 1,179,648 bf16
static const size_t TOTAL_SCRATCH = OFF_WP + WP_FLOATS;

__device__ float g_scratch[TOTAL_SCRATCH];

// Prepped-weight offsets in bf16 elements. Each weight block: hi[K*Nd] then lo[K*Nd].
#define WPO_BW1A 0
#define WPO_BW1B 98304
#define WPO_BW1C 196608
#define WPO_BW2  294912
#define WPO_AW1  393216
#define WPO_AW2  688128
#define WPO_GW1  786432
#define WPO_GW2  1081344

// ---------------------------------------------------------------------------
// PTX helpers (all arch-agnostic: ldmatrix sm_75+, bf16 mma sm_80+)
// ---------------------------------------------------------------------------
__device__ __forceinline__ uint32_t smem_u32(const void* p) {
    uint32_t a;
    asm("{ .reg .u64 t; cvta.to.shared.u64 t, %1; cvt.u32.u64 %0, t; }" : "=r"(a) : "l"(p));
    return a;
}
__device__ __forceinline__ void ldsm4(uint32_t (&r)[4], uint32_t addr) {
    asm volatile("ldmatrix.sync.aligned.m8n8.x4.shared.b16 {%0,%1,%2,%3}, [%4];"
                 : "=r"(r[0]), "=r"(r[1]), "=r"(r[2]), "=r"(r[3]) : "r"(addr));
}
__device__ __forceinline__ void ldsm4t(uint32_t (&r)[4], uint32_t addr) {
    asm volatile("ldmatrix.sync.aligned.m8n8.x4.trans.shared.b16 {%0,%1,%2,%3}, [%4];"
                 : "=r"(r[0]), "=r"(r[1]), "=r"(r[2]), "=r"(r[3]) : "r"(addr));
}
__device__ __forceinline__ void mma16816(float (&c)[4], const uint32_t (&a)[4],
                                         uint32_t b0, uint32_t b1) {
    asm volatile(
        "mma.sync.aligned.m16n8k16.row.col.f32.bf16.bf16.f32 "
        "{%0,%1,%2,%3}, {%4,%5,%6,%7}, {%8,%9}, {%0,%1,%2,%3};"
        : "+f"(c[0]), "+f"(c[1]), "+f"(c[2]), "+f"(c[3])
        : "r"(a[0]), "r"(a[1]), "r"(a[2]), "r"(a[3]), "r"(b0), "r"(b1));
}
__device__ __forceinline__ uint32_t packbf2(float x, float y) {
    __nv_bfloat162 p = __halves2bfloat162(__float2bfloat16(x), __float2bfloat16(y));
    return *(uint32_t*)&p;
}

// ---------------------------------------------------------------------------
// Weight prep: fp32 W[K,Nd] -> dense bf16 hi then lo
// ---------------------------------------------------------------------------
__global__ void prep_weight(const float* __restrict__ W, __nv_bfloat16* __restrict__ out,
                            int total)
{
    int i = blockIdx.x * blockDim.x + threadIdx.x;
    if (i >= total) return;
    float w = W[i];
    __nv_bfloat16 hi = __float2bfloat16(w);
    __nv_bfloat16 lo = __float2bfloat16(w - __bfloat162float(hi));
    out[i] = hi;
    out[total + i] = lo;
}

// ---------------------------------------------------------------------------
// mma.sync GEMM: C[M,Nd] = op(A)[M,K] @ W[K,Nd] (+bias)
// bf16 hi/lo 3-term split (Ahi*Bhi + Alo*Bhi + Ahi*Blo), fp32 accumulate.
//   BNA:   A transformed relu(a*scale[k]+shift[k]) at staging
//   GATH:  epilogue adds Ph[src[r]] + Ph[dst[r]] + U1[gid[src[r]]]
//   SCAT:  epilogue atomicAdds rows into segout[seg[r]]
//   STATS: per-column sum/sumsq into st_sum/st_sq
// 128x128 tile, 256 threads (8 warps as 4x2; warp tile 32x64), KC=32.
// Requires Nd % 128 == 0, K % 32 == 0.
// ---------------------------------------------------------------------------
#define APAD 80     // bytes per A smem row (32 bf16 = 64B + 16B pad)
#define BPAD 272    // bytes per B smem row (128 bf16 = 256B + 16B pad)

template<bool BNA, bool SCAT, bool GATH, bool STATS>
__global__ void __launch_bounds__(256, 1)
gemm_mma(const float* __restrict__ A, const __nv_bfloat16* __restrict__ Bp,
         const float* __restrict__ bias, float* __restrict__ C,
         int M, int K, int Nd,
         const float* __restrict__ bnscale, const float* __restrict__ bnshift,
         const int* __restrict__ seg, float* __restrict__ segout,
         const float* __restrict__ Ph, const float* __restrict__ U1,
         const int* __restrict__ src, const int* __restrict__ dst,
         const int* __restrict__ gid,
         float* __restrict__ st_sum, float* __restrict__ st_sq)
{
    __shared__ __align__(16) char sAhi[128 * APAD];
    __shared__ __align__(16) char sAlo[128 * APAD];
    __shared__ __align__(16) char sBhi[32 * BPAD];
    __shared__ __align__(16) char sBlo[32 * BPAD];
    __shared__ float ssc[HID];
    __shared__ float ssh[HID];
    __shared__ float ssum[128];
    __shared__ float ssq[128];

    const int tid  = threadIdx.x;
    const int wid  = tid >> 5;
    const int lane = tid & 31;
    const int wm   = wid & 3;     // warp row (32 rows)
    const int wn   = wid >> 2;    // warp col (64 cols)
    const int row0 = blockIdx.y * 128;
    const int col0 = blockIdx.x * 128;

    if (BNA) {
        for (int i = tid; i < K; i += 256) { ssc[i] = bnscale[i]; ssh[i] = bnshift[i]; }
    }
    if (STATS && tid < 128) { ssum[tid] = 0.f; ssq[tid] = 0.f; }
    __syncthreads();

    // ---- staging thread mapping ----
    const int arow = tid >> 1;            // 0..127
    const int acol = (tid & 1) * 16;      // 0 or 16
    const bool avalid = (row0 + arow) < M;
    const float* Ap = A + (size_t)(row0 + arow) * K + acol;

    const int brow = tid >> 3;            // 0..31
    const int bcol = (tid & 7) * 16;      // 0..112
    const __nv_bfloat16* Whi = Bp;
    const __nv_bfloat16* Wlo = Bp + (size_t)K * Nd;

    float acc[2][8][4];
    #pragma unroll
    for (int i = 0; i < 2; i++)
        #pragma unroll
        for (int j = 0; j < 8; j++)
            #pragma unroll
            for (int q = 0; q < 4; q++) acc[i][j][q] = 0.f;

    const uint32_t aHiB = smem_u32(sAhi);
    const uint32_t aLoB = smem_u32(sAlo);
    const uint32_t bHiB = smem_u32(sBhi);
    const uint32_t bLoB = smem_u32(sBlo);

    // lane-invariant fragment address parts
    const uint32_t aoff = (uint32_t)((lane & 15) * APAD + (lane >> 4) * 16);
    const uint32_t boff = (uint32_t)((((lane >> 3) & 1) * 8 + (lane & 7)) * BPAD + (lane >> 4) * 16);

    const int nchunk = K >> 5;

    // prefetch chunk 0
    float4 aval[4];
    uint4 bh0, bh1, bl0, bl1;
    {
        if (avalid) {
            #pragma unroll
            for (int q = 0; q < 4; q++) aval[q] = *(const float4*)(Ap + q * 4);
        } else {
            #pragma unroll
            for (int q = 0; q < 4; q++) aval[q] = make_float4(0.f, 0.f, 0.f, 0.f);
        }
        const __nv_bfloat16* bp = Whi + (size_t)brow * Nd + col0 + bcol;
        const __nv_bfloat16* lp = Wlo + (size_t)brow * Nd + col0 + bcol;
        bh0 = *(const uint4*)bp; bh1 = *(const uint4*)(bp + 8);
        bl0 = *(const uint4*)lp; bl1 = *(const uint4*)(lp + 8);
    }

    for (int c = 0; c < nchunk; c++) {
        if (c > 0) __syncthreads();
        // ---- store stage (convert A to hi/lo, copy B) ----
        {
            const int kb = c * 32 + acol;
            char* ah = sAhi + arow * APAD + acol * 2;
            char* al = sAlo + arow * APAD + acol * 2;
            #pragma unroll
            for (int q = 0; q < 4; q++) {
                float4 v = aval[q];
                if (BNA) {
                    const int k = kb + q * 4;
                    v.x = fmaxf(fmaf(v.x, ssc[k + 0], ssh[k + 0]), 0.f);
                    v.y = fmaxf(fmaf(v.y, ssc[k + 1], ssh[k + 1]), 0.f);
                    v.z = fmaxf(fmaf(v.z, ssc[k + 2], ssh[k + 2]), 0.f);
                    v.w = fmaxf(fmaf(v.w, ssc[k + 3], ssh[k + 3]), 0.f);
                }
                float hx = __bfloat162float(__float2bfloat16(v.x));
                float hy = __bfloat162float(__float2bfloat16(v.y));
                float hz = __bfloat162float(__float2bfloat16(v.z));
                float hw = __bfloat162float(__float2bfloat16(v.w));
                uint2 hv, lv;
                hv.x = packbf2(v.x, v.y);
                hv.y = packbf2(v.z, v.w);
                lv.x = packbf2(v.x - hx, v.y - hy);
                lv.y = packbf2(v.z - hz, v.w - hw);
                *(uint2*)(ah + q * 8) = hv;
                *(uint2*)(al + q * 8) = lv;
            }
            char* bh = sBhi + brow * BPAD + bcol * 2;
            char* bl = sBlo + brow * BPAD + bcol * 2;
            *(uint4*)(bh)      = bh0;
            *(uint4*)(bh + 16) = bh1;
            *(uint4*)(bl)      = bl0;
            *(uint4*)(bl + 16) = bl1;
        }
        __syncthreads();
        // ---- prefetch next chunk ----
        if (c + 1 < nchunk) {
            const float* ap = Ap + (c + 1) * 32;
            if (avalid) {
                #pragma unroll
                for (int q = 0; q < 4; q++) aval[q] = *(const float4*)(ap + q * 4);
            }
            const __nv_bfloat16* bp = Whi + (size_t)((c + 1) * 32 + brow) * Nd + col0 + bcol;
            const __nv_bfloat16* lp = Wlo + (size_t)((c + 1) * 32 + brow) * Nd + col0 + bcol;
            bh0 = *(const uint4*)bp; bh1 = *(const uint4*)(bp + 8);
            bl0 = *(const uint4*)lp; bl1 = *(const uint4*)(lp + 8);
        }
        // ---- compute: 2 ksteps x 3 passes x (2m x 8n) mma ----
        #pragma unroll
        for (int kk = 0; kk < 2; kk++) {
            uint32_t ah[2][4], at[2][4], bx[8][2];
            #pragma unroll
            for (int i = 0; i < 2; i++)
                ldsm4(ah[i], aHiB + aoff + (uint32_t)((32 * wm + 16 * i) * APAD + kk * 32));
            #pragma unroll
            for (int p = 0; p < 4; p++) {
                uint32_t r[4];
                ldsm4t(r, bHiB + boff + (uint32_t)(kk * 16 * BPAD + (64 * wn + p * 16) * 2));
                bx[2 * p][0] = r[0]; bx[2 * p][1] = r[1];
                bx[2 * p + 1][0] = r[2]; bx[2 * p + 1][1] = r[3];
            }
            #pragma unroll
            for (int i = 0; i < 2; i++)
                #pragma unroll
                for (int j = 0; j < 8; j++)
                    mma16816(acc[i][j], ah[i], bx[j][0], bx[j][1]);
            #pragma unroll
            for (int i = 0; i < 2; i++)
                ldsm4(at[i], aLoB + aoff + (uint32_t)((32 * wm + 16 * i) * APAD + kk * 32));
            #pragma unroll
            for (int i = 0; i < 2; i++)
                #pragma unroll
                for (int j = 0; j < 8; j++)
                    mma16816(acc[i][j], at[i], bx[j][0], bx[j][1]);
            #pragma unroll
            for (int p = 0; p < 4; p++) {
                uint32_t r[4];
                ldsm4t(r, bLoB + boff + (uint32_t)(kk * 16 * BPAD + (64 * wn + p * 16) * 2));
                bx[2 * p][0] = r[0]; bx[2 * p][1] = r[1];
                bx[2 * p + 1][0] = r[2]; bx[2 * p + 1][1] = r[3];
            }
            #pragma unroll
            for (int i = 0; i < 2; i++)
                #pragma unroll
                for (int j = 0; j < 8; j++)
                    mma16816(acc[i][j], ah[i], bx[j][0], bx[j][1]);
        }
    }

    // ---- epilogue ----
    const int m4 = lane >> 2;
    const int n2 = (lane & 3) * 2;

    float bcolv[16];
    #pragma unroll
    for (int j = 0; j < 8; j++) {
        if (bias) {
            float2 b2 = *(const float2*)(bias + col0 + 64 * wn + 8 * j + n2);
            bcolv[2 * j] = b2.x; bcolv[2 * j + 1] = b2.y;
        } else {
            bcolv[2 * j] = 0.f; bcolv[2 * j + 1] = 0.f;
        }
    }
    float csum[16], csq[16];
    if (STATS) {
        #pragma unroll
        for (int q = 0; q < 16; q++) { csum[q] = 0.f; csq[q] = 0.f; }
    }

    #pragma unroll
    for (int i = 0; i < 2; i++) {
        const int rb = row0 + 32 * wm + 16 * i + m4;
        #pragma unroll
        for (int hf = 0; hf < 2; hf++) {
            const int r = rb + 8 * hf;
            if (r >= M) continue;
            int si = 0, di = 0, gi2 = 0, sg = 0;
            if (GATH) { si = src[r]; di = dst[r]; gi2 = gid[si]; }
            if (SCAT) sg = seg[r];
            #pragma unroll
            for (int j = 0; j < 8; j++) {
                const int gc = col0 + 64 * wn + 8 * j + n2;
                float v0 = acc[i][j][2 * hf]     + bcolv[2 * j];
                float v1 = acc[i][j][2 * hf + 1] + bcolv[2 * j + 1];
                if (GATH) {
                    float2 g1 = *(const float2*)(Ph + (size_t)si * HID + gc);
                    float2 g2 = *(const float2*)(Ph + (size_t)di * HID + gc);
                    float2 g3 = *(const float2*)(U1 + (size_t)gi2 * HID + gc);
                    v0 += g1.x + g2.x + g3.x;
                    v1 += g1.y + g2.y + g3.y;
                }
                *(float2*)(C + (size_t)r * Nd + gc) = make_float2(v0, v1);
                if (SCAT) {
                    float* so = segout + (size_t)sg * Nd + gc;
                    atomicAdd(so, v0); atomicAdd(so + 1, v1);
                }
                if (STATS) {
                    csum[2 * j] += v0;     csq[2 * j] += v0 * v0;
                    csum[2 * j + 1] += v1; csq[2 * j + 1] += v1 * v1;
                }
            }
        }
    }
    if (STATS) {
        #pragma unroll
        for (int j = 0; j < 8; j++) {
            const int cl0 = 64 * wn + 8 * j + n2;
            atomicAdd(&ssum[cl0], csum[2 * j]);
            atomicAdd(&ssum[cl0 + 1], csum[2 * j + 1]);
            atomicAdd(&ssq[cl0], csq[2 * j]);
            atomicAdd(&ssq[cl0 + 1], csq[2 * j + 1]);
        }
        __syncthreads();
        if (tid < 128) {
            atomicAdd(&st_sum[col0 + tid], ssum[tid]);
            atomicAdd(&st_sq[col0 + tid], ssq[tid]);
        }
    }
}

// ---------------------------------------------------------------------------
// Elementwise / scatter kernels
// ---------------------------------------------------------------------------
__global__ void zerok(float* __restrict__ p, size_t n) {
    size_t i = (size_t)blockIdx.x * blockDim.x + threadIdx.x;
    size_t st = (size_t)gridDim.x * blockDim.x;
    for (; i < n; i += st) p[i] = 0.f;
}

__global__ void edge_scatter_h(const float* __restrict__ h, const int* __restrict__ src,
                               const int* __restrict__ dst, float* __restrict__ SH, int E)
{
    int idx = blockIdx.x * blockDim.x + threadIdx.x;
    int tot = E * 32;
    if (idx >= tot) return;
    int ei = idx >> 5;
    int c  = (idx & 31) << 2;
    int s = src[ei], d = dst[ei];
    float4 v = *(const float4*)&h[(size_t)s * D + c];
    float* o = SH + (size_t)d * D + c;
    atomicAdd(o + 0, v.x); atomicAdd(o + 1, v.y);
    atomicAdd(o + 2, v.z); atomicAdd(o + 3, v.w);
}

__global__ void bn_prep(float* __restrict__ sum, float* __restrict__ sq,
                        const float* __restrict__ g1, const float* __restrict__ beta1,
                        float* __restrict__ scale, float* __restrict__ shift, float invM)
{
    const int c = threadIdx.x;
    float mean = sum[c] * invM;
    float var  = sq[c] * invM - mean * mean;
    float rstd = rsqrtf(var + 1e-5f);
    float sc = rstd * g1[c];
    scale[c] = sc;
    shift[c] = beta1[c] - mean * sc;
    sum[c] = 0.f;
    sq[c] = 0.f;
}

__global__ void node_build(const float* __restrict__ h, const float* __restrict__ u,
                           const int* __restrict__ gid,
                           const float* __restrict__ SH, const float* __restrict__ SE,
                           float* __restrict__ Xa, float* __restrict__ UE, int N)
{
    int idx = blockIdx.x * blockDim.x + threadIdx.x;
    int tot = N * 32;
    if (idx >= tot) return;
    int n = idx >> 5;
    int c = (idx & 31) << 2;
    int g = gid[n];
    float4 sh = *(const float4*)&SH[(size_t)n * D + c];
    float4 hv = *(const float4*)&h[(size_t)n * D + c];
    float4 se = *(const float4*)&SE[(size_t)n * D + c];
    float4 uv = *(const float4*)&u[(size_t)g * D + c];
    size_t base = (size_t)n * HID;
    *(float4*)&Xa[base + c]         = make_float4(sh.x + hv.x, sh.y + hv.y, sh.z + hv.z, sh.w + hv.w);
    *(float4*)&Xa[base + D + c]     = se;
    *(float4*)&Xa[base + 2 * D + c] = uv;
    float* o = UE + (size_t)g * D + c;
    atomicAdd(o + 0, 0.5f * se.x); atomicAdd(o + 1, 0.5f * se.y);
    atomicAdd(o + 2, 0.5f * se.z); atomicAdd(o + 3, 0.5f * se.w);
}

__global__ void graph_build(const float* __restrict__ u, const float* __restrict__ UH,
                            const float* __restrict__ UE, float* __restrict__ Xg, int G)
{
    int idx = blockIdx.x * blockDim.x + threadIdx.x;
    int tot = G * 32;
    if (idx >= tot) return;
    int g = idx >> 5;
    int c = (idx & 31) << 2;
    size_t base = (size_t)g * HID;
    *(float4*)&Xg[base + c]         = *(const float4*)&UH[(size_t)g * D + c];
    *(float4*)&Xg[base + D + c]     = *(const float4*)&UE[(size_t)g * D + c];
    *(float4*)&Xg[base + 2 * D + c] = *(const float4*)&u[(size_t)g * D + c];
}

// ---------------------------------------------------------------------------
// Dispatch. mode: 0 plain, 1 GATH+STATS, 2 BNA+SCAT, 3 STATS, 4 BNA
// ---------------------------------------------------------------------------
static void run_gemm_mma(int mode,
                         const float* A, const __nv_bfloat16* Bp, const float* bias, float* C,
                         int M, int K, int Nd,
                         const float* sc, const float* sh,
                         const int* seg, float* segout,
                         const float* Ph, const float* U1,
                         const int* src, const int* dst, const int* gid,
                         float* st_sum, float* st_sq)
{
    dim3 grid(Nd / 128, (M + 127) / 128);
    switch (mode) {
    case 0: gemm_mma<false,false,false,false><<<grid,256>>>(A,Bp,bias,C,M,K,Nd,sc,sh,seg,segout,Ph,U1,src,dst,gid,st_sum,st_sq); break;
    case 1: gemm_mma<false,false,true, true ><<<grid,256>>>(A,Bp,bias,C,M,K,Nd,sc,sh,seg,segout,Ph,U1,src,dst,gid,st_sum,st_sq); break;
    case 2: gemm_mma<true, true, false,false><<<grid,256>>>(A,Bp,bias,C,M,K,Nd,sc,sh,seg,segout,Ph,U1,src,dst,gid,st_sum,st_sq); break;
    case 3: gemm_mma<false,false,false,true ><<<grid,256>>>(A,Bp,bias,C,M,K,Nd,sc,sh,seg,segout,Ph,U1,src,dst,gid,st_sum,st_sq); break;
    case 4: gemm_mma<true, false,false,false><<<grid,256>>>(A,Bp,bias,C,M,K,Nd,sc,sh,seg,segout,Ph,U1,src,dst,gid,st_sum,st_sq); break;
    }
}

extern "C" void kernel_launch(void* const* d_in, const int* in_sizes, int n_in,
                              void* d_out, int out_size)
{
    const float* h   = (const float*)d_in[0];
    const float* e   = (const float*)d_in[1];
    const float* u   = (const float*)d_in[2];
    const int*   src = (const int*)d_in[3];
    const int*   dst = (const int*)d_in[4];
    const int*   gid = (const int*)d_in[5];

    const float* bW1 = (const float*)d_in[6];
    const float* bb1 = (const float*)d_in[7];
    const float* bg1 = (const float*)d_in[8];
    const float* bbt = (const float*)d_in[9];
    const float* bW2 = (const float*)d_in[10];
    const float* bb2 = (const float*)d_in[11];

    const float* aW1 = (const float*)d_in[12];
    const float* ab1 = (const float*)d_in[13];
    const float* ag1 = (const float*)d_in[14];
    const float* abt = (const float*)d_in[15];
    const float* aW2 = (const float*)d_in[16];
    const float* ab2 = (const float*)d_in[17];

    const float* gW1 = (const float*)d_in[18];
    const float* gb1 = (const float*)d_in[19];
    const float* gg1 = (const float*)d_in[20];
    const float* gbt = (const float*)d_in[21];
    const float* gW2 = (const float*)d_in[22];
    const float* gb2 = (const float*)d_in[23];

    const int N = in_sizes[5];
    const int E = in_sizes[3];
    const int G = in_sizes[2] / D;

    float* scratch = nullptr;
    cudaGetSymbolAddress((void**)&scratch, g_scratch);

    float* Zb = scratch + OFF_ZB;
    float* Ph = scratch + OFF_PH;
    float* U1 = scratch + OFF_U1;
    float* Xa = scratch + OFF_XA;
    float* Za = scratch + OFF_ZA;
    float* Xg = scratch + OFF_XG;
    float* Zg = scratch + OFF_ZG;
    float* SH = scratch + OFF_SH;
    float* SE = scratch + OFF_SE;
    float* UH = scratch + OFF_UH;
    float* UE = scratch + OFF_UE;
    float* st_sum   = scratch + OFF_ST;
    float* st_sq    = st_sum + HID;
    float* bn_scale = st_sq + HID;
    float* bn_shift = bn_scale + HID;
    __nv_bfloat16* WP = (__nv_bfloat16*)(scratch + OFF_WP);

    float* out_h = (float*)d_out;
    float* out_e = out_h + (size_t)N * D;
    float* out_u = out_e + (size_t)E * D;

    // Zero accumulators (SH, SE, UH, UE, stats) — contiguous region.
    {
        size_t nz = (size_t)MAXN * D * 2 + (size_t)MAXG * D * 2 + 2 * HID;
        zerok<<<2048, 256>>>(SH, nz);
    }

    // Pre-convert all weights to dense bf16 hi/lo.
    {
        const int T1 = 128 * HID, T2 = HID * HID, T3 = HID * D;
        prep_weight<<<(T1 + 255) / 256, 256>>>(bW1,                       WP + WPO_BW1A, T1);
        prep_weight<<<(T1 + 255) / 256, 256>>>(bW1 + (size_t)D * HID,     WP + WPO_BW1B, T1);
        prep_weight<<<(T1 + 255) / 256, 256>>>(bW1 + (size_t)2 * D * HID, WP + WPO_BW1C, T1);
        prep_weight<<<(T3 + 255) / 256, 256>>>(bW2, WP + WPO_BW2, T3);
        prep_weight<<<(T2 + 255) / 256, 256>>>(aW1, WP + WPO_AW1, T2);
        prep_weight<<<(T3 + 255) / 256, 256>>>(aW2, WP + WPO_AW2, T3);
        prep_weight<<<(T2 + 255) / 256, 256>>>(gW1, WP + WPO_GW1, T2);
        prep_weight<<<(T3 + 255) / 256, 256>>>(gW2, WP + WPO_GW2, T3);
    }

    // ---- Bond path ----
    run_gemm_mma(0, h, WP + WPO_BW1A, nullptr, Ph, N, 128, HID,
                 nullptr, nullptr, nullptr, nullptr, nullptr, nullptr, nullptr, nullptr, nullptr, nullptr, nullptr);
    run_gemm_mma(0, u, WP + WPO_BW1C, bb1, U1, G, 128, HID,
                 nullptr, nullptr, nullptr, nullptr, nullptr, nullptr, nullptr, nullptr, nullptr, nullptr, nullptr);
    edge_scatter_h<<<(E * 32 + 255) / 256, 256>>>(h, src, dst, SH, E);
    // Zb = e@bW1b + Ph[src] + Ph[dst] + U1[gid[src]]; fused stats
    run_gemm_mma(1, e, WP + WPO_BW1B, nullptr, Zb, E, 128, HID,
                 nullptr, nullptr, nullptr, nullptr, Ph, U1, src, dst, gid, st_sum, st_sq);
    bn_prep<<<1, HID>>>(st_sum, st_sq, bg1, bbt, bn_scale, bn_shift, 1.f / (float)E);
    // e_new = relu(BN(Zb)) @ bW2 + bb2 ; SE[dst] += e_new
    run_gemm_mma(2, Zb, WP + WPO_BW2, bb2, out_e, E, HID, D,
                 bn_scale, bn_shift, dst, SE, nullptr, nullptr, nullptr, nullptr, nullptr, nullptr, nullptr);

    // ---- Atom path ----
    node_build<<<(N * 32 + 255) / 256, 256>>>(h, u, gid, SH, SE, Xa, UE, N);
    run_gemm_mma(3, Xa, WP + WPO_AW1, ab1, Za, N, HID, HID,
                 nullptr, nullptr, nullptr, nullptr, nullptr, nullptr, nullptr, nullptr, nullptr, st_sum, st_sq);
    bn_prep<<<1, HID>>>(st_sum, st_sq, ag1, abt, bn_scale, bn_shift, 1.f / (float)N);
    run_gemm_mma(2, Za, WP + WPO_AW2, ab2, out_h, N, HID, D,
                 bn_scale, bn_shift, gid, UH, nullptr, nullptr, nullptr, nullptr, nullptr, nullptr, nullptr);

    // ---- Global path ----
    graph_build<<<(G * 32 + 255) / 256, 256>>>(u, UH, UE, Xg, G);
    run_gemm_mma(3, Xg, WP + WPO_GW1, gb1, Zg, G, HID, HID,
                 nullptr, nullptr, nullptr, nullptr, nullptr, nullptr, nullptr, nullptr, nullptr, st_sum, st_sq);
    bn_prep<<<1, HID>>>(st_sum, st_sq, gg1, gbt, bn_scale, bn_shift, 1.f / (float)G);
    run_gemm_mma(4, Zg, WP + WPO_GW2, gb2, out_u, G, HID, D,
                 bn_scale, bn_shift, nullptr, nullptr, nullptr, nullptr, nullptr, nullptr, nullptr, nullptr, nullptr);
}

// round 6
// speedup vs baseline: 1.4009x; 1.0875x over previous
#include <cuda_runtime.h>
#include <cuda_fp16.h>
#include <cstdint>
#include <cstddef>

#define D 128
#define HID 384
#define MAXN 100000
#define MAXE 500000
#define MAXG 5000

// ---------------------------------------------------------------------------
// Scratch layout (floats)
// ---------------------------------------------------------------------------
static const size_t OFF_ZB = 0;
static const size_t OFF_PH = OFF_ZB + (size_t)MAXE * HID;
static const size_t OFF_U1 = OFF_PH + (size_t)MAXN * HID;
static const size_t OFF_XA = OFF_U1 + (size_t)MAXG * HID;
static const size_t OFF_ZA = OFF_XA + (size_t)MAXN * HID;
static const size_t OFF_XG = OFF_ZA + (size_t)MAXN * HID;
static const size_t OFF_ZG = OFF_XG + (size_t)MAXG * HID;
static const size_t OFF_SH = OFF_ZG + (size_t)MAXG * HID;
static const size_t OFF_SE = OFF_SH + (size_t)MAXN * D;
static const size_t OFF_UH = OFF_SE + (size_t)MAXN * D;
static const size_t OFF_UE = OFF_UH + (size_t)MAXG * D;
static const size_t OFF_ST = OFF_UE + (size_t)MAXG * D;
static const size_t OFF_WP = OFF_ST + 4 * HID;   // prepped weights (fp16, hi only)
static const size_t WP_FLOATS = 294912;          // 589,824 halves
static const size_t TOTAL_SCRATCH = OFF_WP + WP_FLOATS;

__device__ float g_scratch[TOTAL_SCRATCH];

// Prepped-weight offsets in half elements (dense fp16).
#define WPO_BW1A 0
#define WPO_BW1B 49152
#define WPO_BW1C 98304
#define WPO_BW2  147456
#define WPO_AW1  196608
#define WPO_AW2  344064
#define WPO_GW1  393216
#define WPO_GW2  540672

// ---------------------------------------------------------------------------
// PTX helpers (arch-agnostic: ldmatrix sm_75+, fp16 mma sm_80+)
// ---------------------------------------------------------------------------
__device__ __forceinline__ uint32_t smem_u32(const void* p) {
    uint32_t a;
    asm("{ .reg .u64 t; cvta.to.shared.u64 t, %1; cvt.u32.u64 %0, t; }" : "=r"(a) : "l"(p));
    return a;
}
__device__ __forceinline__ void ldsm4(uint32_t (&r)[4], uint32_t addr) {
    asm volatile("ldmatrix.sync.aligned.m8n8.x4.shared.b16 {%0,%1,%2,%3}, [%4];"
                 : "=r"(r[0]), "=r"(r[1]), "=r"(r[2]), "=r"(r[3]) : "r"(addr));
}
__device__ __forceinline__ void ldsm4t(uint32_t (&r)[4], uint32_t addr) {
    asm volatile("ldmatrix.sync.aligned.m8n8.x4.trans.shared.b16 {%0,%1,%2,%3}, [%4];"
                 : "=r"(r[0]), "=r"(r[1]), "=r"(r[2]), "=r"(r[3]) : "r"(addr));
}
__device__ __forceinline__ void mma16816(float (&c)[4], const uint32_t (&a)[4],
                                         uint32_t b0, uint32_t b1) {
    asm volatile(
        "mma.sync.aligned.m16n8k16.row.col.f32.f16.f16.f32 "
        "{%0,%1,%2,%3}, {%4,%5,%6,%7}, {%8,%9}, {%0,%1,%2,%3};"
        : "+f"(c[0]), "+f"(c[1]), "+f"(c[2]), "+f"(c[3])
        : "r"(a[0]), "r"(a[1]), "r"(a[2]), "r"(a[3]), "r"(b0), "r"(b1));
}
__device__ __forceinline__ uint32_t packh2(float x, float y) {
    __half2 p = __halves2half2(__float2half_rn(x), __float2half_rn(y));
    return *(uint32_t*)&p;
}

// ---------------------------------------------------------------------------
// Weight prep: fp32 W -> dense fp16 (single precision-truncated copy)
// ---------------------------------------------------------------------------
__global__ void prep_weight(const float* __restrict__ W, __half* __restrict__ out,
                            int total)
{
    int i = blockIdx.x * blockDim.x + threadIdx.x;
    if (i >= total) return;
    out[i] = __float2half_rn(W[i]);
}

// ---------------------------------------------------------------------------
// mma.sync GEMM: C[M,Nd] = op(A)[M,K] @ W[K,Nd] (+bias)
// fp16 2-pass split: A = Ahi + Alo (exact to ~2^-22), B = fp16(W).
// C ~= Ahi*B + Alo*B, fp32 accumulate. Dropped error ~1.4e-4 (validated model).
//   BNA:   A transformed relu(a*scale[k]+shift[k]) at staging
//   GATH:  epilogue adds Ph[src[r]] + Ph[dst[r]] + U1[gid[src[r]]]
//   SCAT:  epilogue atomicAdds rows into segout[seg[r]]
//   STATS: per-column sum/sumsq into st_sum/st_sq
// 128x128 tile, 256 threads (8 warps as 4x2; warp tile 32x64), KC=32.
// Requires Nd % 128 == 0, K % 32 == 0.
// ---------------------------------------------------------------------------
#define APAD 80     // bytes per A smem row (32 fp16 = 64B + 16B pad)
#define BPAD 272    // bytes per B smem row (128 fp16 = 256B + 16B pad)

template<bool BNA, bool SCAT, bool GATH, bool STATS>
__global__ void __launch_bounds__(256, 1)
gemm_mma(const float* __restrict__ A, const __half* __restrict__ Bp,
         const float* __restrict__ bias, float* __restrict__ C,
         int M, int K, int Nd,
         const float* __restrict__ bnscale, const float* __restrict__ bnshift,
         const int* __restrict__ seg, float* __restrict__ segout,
         const float* __restrict__ Ph, const float* __restrict__ U1,
         const int* __restrict__ src, const int* __restrict__ dst,
         const int* __restrict__ gid,
         float* __restrict__ st_sum, float* __restrict__ st_sq)
{
    __shared__ __align__(16) char sAhi[128 * APAD];
    __shared__ __align__(16) char sAlo[128 * APAD];
    __shared__ __align__(16) char sBhi[32 * BPAD];
    __shared__ float ssc[HID];
    __shared__ float ssh[HID];
    __shared__ float ssum[128];
    __shared__ float ssq[128];

    const int tid  = threadIdx.x;
    const int wid  = tid >> 5;
    const int lane = tid & 31;
    const int wm   = wid & 3;     // warp row (32 rows)
    const int wn   = wid >> 2;    // warp col (64 cols)
    const int row0 = blockIdx.y * 128;
    const int col0 = blockIdx.x * 128;

    if (BNA) {
        for (int i = tid; i < K; i += 256) { ssc[i] = bnscale[i]; ssh[i] = bnshift[i]; }
    }
    if (STATS && tid < 128) { ssum[tid] = 0.f; ssq[tid] = 0.f; }
    __syncthreads();

    // ---- staging thread mapping ----
    const int arow = tid >> 1;            // 0..127
    const int acol = (tid & 1) * 16;      // 0 or 16
    const bool avalid = (row0 + arow) < M;
    const float* Ap = A + (size_t)(row0 + arow) * K + acol;

    const int brow = tid >> 3;            // 0..31
    const int bcol = (tid & 7) * 16;      // 0..112

    float acc[2][8][4];
    #pragma unroll
    for (int i = 0; i < 2; i++)
        #pragma unroll
        for (int j = 0; j < 8; j++)
            #pragma unroll
            for (int q = 0; q < 4; q++) acc[i][j][q] = 0.f;

    const uint32_t aHiB = smem_u32(sAhi);
    const uint32_t aLoB = smem_u32(sAlo);
    const uint32_t bHiB = smem_u32(sBhi);

    // lane-invariant fragment address parts
    const uint32_t aoff = (uint32_t)((lane & 15) * APAD + (lane >> 4) * 16);
    const uint32_t boff = (uint32_t)((((lane >> 3) & 1) * 8 + (lane & 7)) * BPAD + (lane >> 4) * 16);

    const int nchunk = K >> 5;

    // prefetch chunk 0
    float4 aval[4];
    uint4 bh0, bh1;
    {
        if (avalid) {
            #pragma unroll
            for (int q = 0; q < 4; q++) aval[q] = *(const float4*)(Ap + q * 4);
        } else {
            #pragma unroll
            for (int q = 0; q < 4; q++) aval[q] = make_float4(0.f, 0.f, 0.f, 0.f);
        }
        const __half* bp = Bp + (size_t)brow * Nd + col0 + bcol;
        bh0 = *(const uint4*)bp; bh1 = *(const uint4*)(bp + 8);
    }

    for (int c = 0; c < nchunk; c++) {
        if (c > 0) __syncthreads();
        // ---- store stage (convert A to fp16 hi/lo, copy B) ----
        {
            const int kb = c * 32 + acol;
            char* ah = sAhi + arow * APAD + acol * 2;
            char* al = sAlo + arow * APAD + acol * 2;
            #pragma unroll
            for (int q = 0; q < 4; q++) {
                float4 v = aval[q];
                if (BNA) {
                    const int k = kb + q * 4;
                    v.x = fmaxf(fmaf(v.x, ssc[k + 0], ssh[k + 0]), 0.f);
                    v.y = fmaxf(fmaf(v.y, ssc[k + 1], ssh[k + 1]), 0.f);
                    v.z = fmaxf(fmaf(v.z, ssc[k + 2], ssh[k + 2]), 0.f);
                    v.w = fmaxf(fmaf(v.w, ssc[k + 3], ssh[k + 3]), 0.f);
                }
                float hx = __half2float(__float2half_rn(v.x));
                float hy = __half2float(__float2half_rn(v.y));
                float hz = __half2float(__float2half_rn(v.z));
                float hw = __half2float(__float2half_rn(v.w));
                uint2 hv, lv;
                hv.x = packh2(v.x, v.y);
                hv.y = packh2(v.z, v.w);
                lv.x = packh2(v.x - hx, v.y - hy);
                lv.y = packh2(v.z - hz, v.w - hw);
                *(uint2*)(ah + q * 8) = hv;
                *(uint2*)(al + q * 8) = lv;
            }
            char* bh = sBhi + brow * BPAD + bcol * 2;
            *(uint4*)(bh)      = bh0;
            *(uint4*)(bh + 16) = bh1;
        }
        __syncthreads();
        // ---- prefetch next chunk ----
        if (c + 1 < nchunk) {
            const float* ap = Ap + (c + 1) * 32;
            if (avalid) {
                #pragma unroll
                for (int q = 0; q < 4; q++) aval[q] = *(const float4*)(ap + q * 4);
            }
            const __half* bp = Bp + (size_t)((c + 1) * 32 + brow) * Nd + col0 + bcol;
            bh0 = *(const uint4*)bp; bh1 = *(const uint4*)(bp + 8);
        }
        // ---- compute: 2 ksteps x 2 passes x (2m x 8n) mma ----
        #pragma unroll
        for (int kk = 0; kk < 2; kk++) {
            uint32_t ah[2][4], at[2][4], bx[8][2];
            #pragma unroll
            for (int i = 0; i < 2; i++)
                ldsm4(ah[i], aHiB + aoff + (uint32_t)((32 * wm + 16 * i) * APAD + kk * 32));
            #pragma unroll
            for (int i = 0; i < 2; i++)
                ldsm4(at[i], aLoB + aoff + (uint32_t)((32 * wm + 16 * i) * APAD + kk * 32));
            #pragma unroll
            for (int p = 0; p < 4; p++) {
                uint32_t r[4];
                ldsm4t(r, bHiB + boff + (uint32_t)(kk * 16 * BPAD + (64 * wn + p * 16) * 2));
                bx[2 * p][0] = r[0]; bx[2 * p][1] = r[1];
                bx[2 * p + 1][0] = r[2]; bx[2 * p + 1][1] = r[3];
            }
            #pragma unroll
            for (int i = 0; i < 2; i++)
                #pragma unroll
                for (int j = 0; j < 8; j++)
                    mma16816(acc[i][j], ah[i], bx[j][0], bx[j][1]);
            #pragma unroll
            for (int i = 0; i < 2; i++)
                #pragma unroll
                for (int j = 0; j < 8; j++)
                    mma16816(acc[i][j], at[i], bx[j][0], bx[j][1]);
        }
    }

    // ---- epilogue ----
    const int m4 = lane >> 2;
    const int n2 = (lane & 3) * 2;

    float bcolv[16];
    #pragma unroll
    for (int j = 0; j < 8; j++) {
        if (bias) {
            float2 b2 = *(const float2*)(bias + col0 + 64 * wn + 8 * j + n2);
            bcolv[2 * j] = b2.x; bcolv[2 * j + 1] = b2.y;
        } else {
            bcolv[2 * j] = 0.f; bcolv[2 * j + 1] = 0.f;
        }
    }
    float csum[16], csq[16];
    if (STATS) {
        #pragma unroll
        for (int q = 0; q < 16; q++) { csum[q] = 0.f; csq[q] = 0.f; }
    }

    #pragma unroll
    for (int i = 0; i < 2; i++) {
        const int rb = row0 + 32 * wm + 16 * i + m4;
        #pragma unroll
        for (int hf = 0; hf < 2; hf++) {
            const int r = rb + 8 * hf;
            if (r >= M) continue;
            int si = 0, di = 0, gi2 = 0, sg = 0;
            if (GATH) { si = src[r]; di = dst[r]; gi2 = gid[si]; }
            if (SCAT) sg = seg[r];
            #pragma unroll
            for (int j = 0; j < 8; j++) {
                const int gc = col0 + 64 * wn + 8 * j + n2;
                float v0 = acc[i][j][2 * hf]     + bcolv[2 * j];
                float v1 = acc[i][j][2 * hf + 1] + bcolv[2 * j + 1];
                if (GATH) {
                    float2 g1 = *(const float2*)(Ph + (size_t)si * HID + gc);
                    float2 g2 = *(const float2*)(Ph + (size_t)di * HID + gc);
                    float2 g3 = *(const float2*)(U1 + (size_t)gi2 * HID + gc);
                    v0 += g1.x + g2.x + g3.x;
                    v1 += g1.y + g2.y + g3.y;
                }
                *(float2*)(C + (size_t)r * Nd + gc) = make_float2(v0, v1);
                if (SCAT) {
                    float* so = segout + (size_t)sg * Nd + gc;
                    atomicAdd(so, v0); atomicAdd(so + 1, v1);
                }
                if (STATS) {
                    csum[2 * j] += v0;     csq[2 * j] += v0 * v0;
                    csum[2 * j + 1] += v1; csq[2 * j + 1] += v1 * v1;
                }
            }
        }
    }
    if (STATS) {
        #pragma unroll
        for (int j = 0; j < 8; j++) {
            const int cl0 = 64 * wn + 8 * j + n2;
            atomicAdd(&ssum[cl0], csum[2 * j]);
            atomicAdd(&ssum[cl0 + 1], csum[2 * j + 1]);
            atomicAdd(&ssq[cl0], csq[2 * j]);
            atomicAdd(&ssq[cl0 + 1], csq[2 * j + 1]);
        }
        __syncthreads();
        if (tid < 128) {
            atomicAdd(&st_sum[col0 + tid], ssum[tid]);
            atomicAdd(&st_sq[col0 + tid], ssq[tid]);
        }
    }
}

// ---------------------------------------------------------------------------
// Elementwise / scatter kernels
// ---------------------------------------------------------------------------
__global__ void zerok(float* __restrict__ p, size_t n) {
    size_t i = (size_t)blockIdx.x * blockDim.x + threadIdx.x;
    size_t st = (size_t)gridDim.x * blockDim.x;
    for (; i < n; i += st) p[i] = 0.f;
}

__global__ void edge_scatter_h(const float* __restrict__ h, const int* __restrict__ src,
                               const int* __restrict__ dst, float* __restrict__ SH, int E)
{
    int idx = blockIdx.x * blockDim.x + threadIdx.x;
    int tot = E * 32;
    if (idx >= tot) return;
    int ei = idx >> 5;
    int c  = (idx & 31) << 2;
    int s = src[ei], d = dst[ei];
    float4 v = *(const float4*)&h[(size_t)s * D + c];
    float* o = SH + (size_t)d * D + c;
    atomicAdd(o + 0, v.x); atomicAdd(o + 1, v.y);
    atomicAdd(o + 2, v.z); atomicAdd(o + 3, v.w);
}

__global__ void bn_prep(float* __restrict__ sum, float* __restrict__ sq,
                        const float* __restrict__ g1, const float* __restrict__ beta1,
                        float* __restrict__ scale, float* __restrict__ shift, float invM)
{
    const int c = threadIdx.x;
    float mean = sum[c] * invM;
    float var  = sq[c] * invM - mean * mean;
    float rstd = rsqrtf(var + 1e-5f);
    float sc = rstd * g1[c];
    scale[c] = sc;
    shift[c] = beta1[c] - mean * sc;
    sum[c] = 0.f;
    sq[c] = 0.f;
}

__global__ void node_build(const float* __restrict__ h, const float* __restrict__ u,
                           const int* __restrict__ gid,
                           const float* __restrict__ SH, const float* __restrict__ SE,
                           float* __restrict__ Xa, float* __restrict__ UE, int N)
{
    int idx = blockIdx.x * blockDim.x + threadIdx.x;
    int tot = N * 32;
    if (idx >= tot) return;
    int n = idx >> 5;
    int c = (idx & 31) << 2;
    int g = gid[n];
    float4 sh = *(const float4*)&SH[(size_t)n * D + c];
    float4 hv = *(const float4*)&h[(size_t)n * D + c];
    float4 se = *(const float4*)&SE[(size_t)n * D + c];
    float4 uv = *(const float4*)&u[(size_t)g * D + c];
    size_t base = (size_t)n * HID;
    *(float4*)&Xa[base + c]         = make_float4(sh.x + hv.x, sh.y + hv.y, sh.z + hv.z, sh.w + hv.w);
    *(float4*)&Xa[base + D + c]     = se;
    *(float4*)&Xa[base + 2 * D + c] = uv;
    float* o = UE + (size_t)g * D + c;
    atomicAdd(o + 0, 0.5f * se.x); atomicAdd(o + 1, 0.5f * se.y);
    atomicAdd(o + 2, 0.5f * se.z); atomicAdd(o + 3, 0.5f * se.w);
}

__global__ void graph_build(const float* __restrict__ u, const float* __restrict__ UH,
                            const float* __restrict__ UE, float* __restrict__ Xg, int G)
{
    int idx = blockIdx.x * blockDim.x + threadIdx.x;
    int tot = G * 32;
    if (idx >= tot) return;
    int g = idx >> 5;
    int c = (idx & 31) << 2;
    size_t base = (size_t)g * HID;
    *(float4*)&Xg[base + c]         = *(const float4*)&UH[(size_t)g * D + c];
    *(float4*)&Xg[base + D + c]     = *(const float4*)&UE[(size_t)g * D + c];
    *(float4*)&Xg[base + 2 * D + c] = *(const float4*)&u[(size_t)g * D + c];
}

// ---------------------------------------------------------------------------
// Dispatch. mode: 0 plain, 1 GATH+STATS, 2 BNA+SCAT, 3 STATS, 4 BNA
// ---------------------------------------------------------------------------
static void run_gemm_mma(int mode,
                         const float* A, const __half* Bp, const float* bias, float* C,
                         int M, int K, int Nd,
                         const float* sc, const float* sh,
                         const int* seg, float* segout,
                         const float* Ph, const float* U1,
                         const int* src, const int* dst, const int* gid,
                         float* st_sum, float* st_sq)
{
    dim3 grid(Nd / 128, (M + 127) / 128);
    switch (mode) {
    case 0: gemm_mma<false,false,false,false><<<grid,256>>>(A,Bp,bias,C,M,K,Nd,sc,sh,seg,segout,Ph,U1,src,dst,gid,st_sum,st_sq); break;
    case 1: gemm_mma<false,false,true, true ><<<grid,256>>>(A,Bp,bias,C,M,K,Nd,sc,sh,seg,segout,Ph,U1,src,dst,gid,st_sum,st_sq); break;
    case 2: gemm_mma<true, true, false,false><<<grid,256>>>(A,Bp,bias,C,M,K,Nd,sc,sh,seg,segout,Ph,U1,src,dst,gid,st_sum,st_sq); break;
    case 3: gemm_mma<false,false,false,true ><<<grid,256>>>(A,Bp,bias,C,M,K,Nd,sc,sh,seg,segout,Ph,U1,src,dst,gid,st_sum,st_sq); break;
    case 4: gemm_mma<true, false,false,false><<<grid,256>>>(A,Bp,bias,C,M,K,Nd,sc,sh,seg,segout,Ph,U1,src,dst,gid,st_sum,st_sq); break;
    }
}

extern "C" void kernel_launch(void* const* d_in, const int* in_sizes, int n_in,
                              void* d_out, int out_size)
{
    const float* h   = (const float*)d_in[0];
    const float* e   = (const float*)d_in[1];
    const float* u   = (const float*)d_in[2];
    const int*   src = (const int*)d_in[3];
    const int*   dst = (const int*)d_in[4];
    const int*   gid = (const int*)d_in[5];

    const float* bW1 = (const float*)d_in[6];
    const float* bb1 = (const float*)d_in[7];
    const float* bg1 = (const float*)d_in[8];
    const float* bbt = (const float*)d_in[9];
    const float* bW2 = (const float*)d_in[10];
    const float* bb2 = (const float*)d_in[11];

    const float* aW1 = (const float*)d_in[12];
    const float* ab1 = (const float*)d_in[13];
    const float* ag1 = (const float*)d_in[14];
    const float* abt = (const float*)d_in[15];
    const float* aW2 = (const float*)d_in[16];
    const float* ab2 = (const float*)d_in[17];

    const float* gW1 = (const float*)d_in[18];
    const float* gb1 = (const float*)d_in[19];
    const float* gg1 = (const float*)d_in[20];
    const float* gbt = (const float*)d_in[21];
    const float* gW2 = (const float*)d_in[22];
    const float* gb2 = (const float*)d_in[23];

    const int N = in_sizes[5];
    const int E = in_sizes[3];
    const int G = in_sizes[2] / D;

    float* scratch = nullptr;
    cudaGetSymbolAddress((void**)&scratch, g_scratch);

    float* Zb = scratch + OFF_ZB;
    float* Ph = scratch + OFF_PH;
    float* U1 = scratch + OFF_U1;
    float* Xa = scratch + OFF_XA;
    float* Za = scratch + OFF_ZA;
    float* Xg = scratch + OFF_XG;
    float* Zg = scratch + OFF_ZG;
    float* SH = scratch + OFF_SH;
    float* SE = scratch + OFF_SE;
    float* UH = scratch + OFF_UH;
    float* UE = scratch + OFF_UE;
    float* st_sum   = scratch + OFF_ST;
    float* st_sq    = st_sum + HID;
    float* bn_scale = st_sq + HID;
    float* bn_shift = bn_scale + HID;
    __half* WP = (__half*)(scratch + OFF_WP);

    float* out_h = (float*)d_out;
    float* out_e = out_h + (size_t)N * D;
    float* out_u = out_e + (size_t)E * D;

    // Zero accumulators (SH, SE, UH, UE, stats) — contiguous region.
    {
        size_t nz = (size_t)MAXN * D * 2 + (size_t)MAXG * D * 2 + 2 * HID;
        zerok<<<2048, 256>>>(SH, nz);
    }

    // Pre-convert all weights to dense fp16.
    {
        const int T1 = 128 * HID, T2 = HID * HID, T3 = HID * D;
        prep_weight<<<(T1 + 255) / 256, 256>>>(bW1,                       WP + WPO_BW1A, T1);
        prep_weight<<<(T1 + 255) / 256, 256>>>(bW1 + (size_t)D * HID,     WP + WPO_BW1B, T1);
        prep_weight<<<(T1 + 255) / 256, 256>>>(bW1 + (size_t)2 * D * HID, WP + WPO_BW1C, T1);
        prep_weight<<<(T3 + 255) / 256, 256>>>(bW2, WP + WPO_BW2, T3);
        prep_weight<<<(T2 + 255) / 256, 256>>>(aW1, WP + WPO_AW1, T2);
        prep_weight<<<(T3 + 255) / 256, 256>>>(aW2, WP + WPO_AW2, T3);
        prep_weight<<<(T2 + 255) / 256, 256>>>(gW1, WP + WPO_GW1, T2);
        prep_weight<<<(T3 + 255) / 256, 256>>>(gW2, WP + WPO_GW2, T3);
    }

    // ---- Bond path ----
    run_gemm_mma(0, h, WP + WPO_BW1A, nullptr, Ph, N, 128, HID,
                 nullptr, nullptr, nullptr, nullptr, nullptr, nullptr, nullptr, nullptr, nullptr, nullptr, nullptr);
    run_gemm_mma(0, u, WP + WPO_BW1C, bb1, U1, G, 128, HID,
                 nullptr, nullptr, nullptr, nullptr, nullptr, nullptr, nullptr, nullptr, nullptr, nullptr, nullptr);
    edge_scatter_h<<<(E * 32 + 255) / 256, 256>>>(h, src, dst, SH, E);
    // Zb = e@bW1b + Ph[src] + Ph[dst] + U1[gid[src]]; fused stats
    run_gemm_mma(1, e, WP + WPO_BW1B, nullptr, Zb, E, 128, HID,
                 nullptr, nullptr, nullptr, nullptr, Ph, U1, src, dst, gid, st_sum, st_sq);
    bn_prep<<<1, HID>>>(st_sum, st_sq, bg1, bbt, bn_scale, bn_shift, 1.f / (float)E);
    // e_new = relu(BN(Zb)) @ bW2 + bb2 ; SE[dst] += e_new
    run_gemm_mma(2, Zb, WP + WPO_BW2, bb2, out_e, E, HID, D,
                 bn_scale, bn_shift, dst, SE, nullptr, nullptr, nullptr, nullptr, nullptr, nullptr, nullptr);

    // ---- Atom path ----
    node_build<<<(N * 32 + 255) / 256, 256>>>(h, u, gid, SH, SE, Xa, UE, N);
    run_gemm_mma(3, Xa, WP + WPO_AW1, ab1, Za, N, HID, HID,
                 nullptr, nullptr, nullptr, nullptr, nullptr, nullptr, nullptr, nullptr, nullptr, st_sum, st_sq);
    bn_prep<<<1, HID>>>(st_sum, st_sq, ag1, abt, bn_scale, bn_shift, 1.f / (float)N);
    run_gemm_mma(2, Za, WP + WPO_AW2, ab2, out_h, N, HID, D,
                 bn_scale, bn_shift, gid, UH, nullptr, nullptr, nullptr, nullptr, nullptr, nullptr, nullptr);

    // ---- Global path ----
    graph_build<<<(G * 32 + 255) / 256, 256>>>(u, UH, UE, Xg, G);
    run_gemm_mma(3, Xg, WP + WPO_GW1, gb1, Zg, G, HID, HID,
                 nullptr, nullptr, nullptr, nullptr, nullptr, nullptr, nullptr, nullptr, nullptr, st_sum, st_sq);
    bn_prep<<<1, HID>>>(st_sum, st_sq, gg1, gbt, bn_scale, bn_shift, 1.f / (float)G);
    run_gemm_mma(4, Zg, WP + WPO_GW2, gb2, out_u, G, HID, D,
                 bn_scale, bn_shift, nullptr, nullptr, nullptr, nullptr, nullptr, nullptr, nullptr, nullptr, nullptr);
}

// round 7
// speedup vs baseline: 1.9964x; 1.4251x over previous
#include <cuda_runtime.h>
#include <cuda_fp16.h>
#include <cstdint>
#include <cstddef>

#define D 128
#define HID 384
#define MAXN 100000
#define MAXE 500000
#define MAXG 5000

// ---------------------------------------------------------------------------
// Scratch layout (floats)
// ---------------------------------------------------------------------------
static const size_t OFF_ZB = 0;
static const size_t OFF_PH = OFF_ZB + (size_t)MAXE * HID;
static const size_t OFF_U1 = OFF_PH + (size_t)MAXN * HID;
static const size_t OFF_XA = OFF_U1 + (size_t)MAXG * HID;
static const size_t OFF_ZA = OFF_XA + (size_t)MAXN * HID;
static const size_t OFF_XG = OFF_ZA + (size_t)MAXN * HID;
static const size_t OFF_ZG = OFF_XG + (size_t)MAXG * HID;
static const size_t OFF_SH = OFF_ZG + (size_t)MAXG * HID;
static const size_t OFF_SE = OFF_SH + (size_t)MAXN * D;
static const size_t OFF_UH = OFF_SE + (size_t)MAXN * D;
static const size_t OFF_UE = OFF_UH + (size_t)MAXG * D;
static const size_t OFF_ST = OFF_UE + (size_t)MAXG * D;
static const size_t OFF_WP = OFF_ST + 4 * HID;   // prepped weights (fp16)
static const size_t WP_FLOATS = 294912;          // 589,824 halves
static const size_t TOTAL_SCRATCH = OFF_WP + WP_FLOATS;

__device__ float g_scratch[TOTAL_SCRATCH];

// Prepped-weight offsets in half elements (dense fp16).
#define WPO_BW1A 0
#define WPO_BW1B 49152
#define WPO_BW1C 98304
#define WPO_BW2  147456
#define WPO_AW1  196608
#define WPO_AW2  344064
#define WPO_GW1  393216
#define WPO_GW2  540672

// ---------------------------------------------------------------------------
// PTX helpers (arch-agnostic: ldmatrix sm_75+, fp16 mma sm_80+, cp.async sm_80+)
// ---------------------------------------------------------------------------
__device__ __forceinline__ uint32_t smem_u32(const void* p) {
    uint32_t a;
    asm("{ .reg .u64 t; cvta.to.shared.u64 t, %1; cvt.u32.u64 %0, t; }" : "=r"(a) : "l"(p));
    return a;
}
__device__ __forceinline__ void ldsm4(uint32_t (&r)[4], uint32_t addr) {
    asm volatile("ldmatrix.sync.aligned.m8n8.x4.shared.b16 {%0,%1,%2,%3}, [%4];"
                 : "=r"(r[0]), "=r"(r[1]), "=r"(r[2]), "=r"(r[3]) : "r"(addr));
}
__device__ __forceinline__ void ldsm4t(uint32_t (&r)[4], uint32_t addr) {
    asm volatile("ldmatrix.sync.aligned.m8n8.x4.trans.shared.b16 {%0,%1,%2,%3}, [%4];"
                 : "=r"(r[0]), "=r"(r[1]), "=r"(r[2]), "=r"(r[3]) : "r"(addr));
}
__device__ __forceinline__ void mma16816(float (&c)[4], const uint32_t (&a)[4],
                                         uint32_t b0, uint32_t b1) {
    asm volatile(
        "mma.sync.aligned.m16n8k16.row.col.f32.f16.f16.f32 "
        "{%0,%1,%2,%3}, {%4,%5,%6,%7}, {%8,%9}, {%0,%1,%2,%3};"
        : "+f"(c[0]), "+f"(c[1]), "+f"(c[2]), "+f"(c[3])
        : "r"(a[0]), "r"(a[1]), "r"(a[2]), "r"(a[3]), "r"(b0), "r"(b1));
}
__device__ __forceinline__ uint32_t packh2(float x, float y) {
    __half2 p = __halves2half2(__float2half_rn(x), __float2half_rn(y));
    return *(uint32_t*)&p;
}
__device__ __forceinline__ void cp_async16(uint32_t saddr, const void* gaddr) {
    asm volatile("cp.async.cg.shared.global [%0], [%1], 16;" :: "r"(saddr), "l"(gaddr));
}
__device__ __forceinline__ void cp_commit() {
    asm volatile("cp.async.commit_group;" ::: "memory");
}
__device__ __forceinline__ void cp_wait0() {
    asm volatile("cp.async.wait_group 0;" ::: "memory");
}
__device__ __forceinline__ void cp_wait1() {
    asm volatile("cp.async.wait_group 1;" ::: "memory");
}

// ---------------------------------------------------------------------------
// Weight prep: fp32 W -> dense fp16
// ---------------------------------------------------------------------------
__global__ void prep_weight(const float* __restrict__ W, __half* __restrict__ out,
                            int total)
{
    int i = blockIdx.x * blockDim.x + threadIdx.x;
    if (i >= total) return;
    out[i] = __float2half_rn(W[i]);
}

// ---------------------------------------------------------------------------
// mma.sync GEMM: C[M,Nd] = op(A)[M,K] @ W[K,Nd] (+bias)
// fp16 2-pass split: A = Ahi + Alo (exact), B = fp16(W). fp32 accumulate.
// 128x128 tile, 256 threads (8 warps as 4x2; warp tile 32x64), KC=32.
// 2 CTAs/SM (launch_bounds 256,2); B staged via double-buffered cp.async.
// Requires Nd % 128 == 0, K % 32 == 0.
// ---------------------------------------------------------------------------
#define APAD 80     // bytes per A smem row (32 fp16 = 64B + 16B pad)
#define BPAD 272    // bytes per B smem row (128 fp16 = 256B + 16B pad)

template<bool BNA, bool SCAT, bool GATH, bool STATS>
__global__ void __launch_bounds__(256, 2)
gemm_mma(const float* __restrict__ A, const __half* __restrict__ Bp,
         const float* __restrict__ bias, float* __restrict__ C,
         int M, int K, int Nd,
         const float* __restrict__ bnscale, const float* __restrict__ bnshift,
         const int* __restrict__ seg, float* __restrict__ segout,
         const float* __restrict__ Ph, const float* __restrict__ U1,
         const int* __restrict__ src, const int* __restrict__ dst,
         const int* __restrict__ gid,
         float* __restrict__ st_sum, float* __restrict__ st_sq)
{
    __shared__ __align__(16) char sAhi[128 * APAD];
    __shared__ __align__(16) char sAlo[128 * APAD];
    __shared__ __align__(16) char sB[2][32 * BPAD];
    __shared__ float ssc[HID];
    __shared__ float ssh[HID];
    __shared__ float ssum[128];
    __shared__ float ssq[128];

    const int tid  = threadIdx.x;
    const int wid  = tid >> 5;
    const int lane = tid & 31;
    const int wm   = wid & 3;     // warp row (32 rows)
    const int wn   = wid >> 2;    // warp col (64 cols)
    const int row0 = blockIdx.y * 128;
    const int col0 = blockIdx.x * 128;

    if (BNA) {
        for (int i = tid; i < K; i += 256) { ssc[i] = bnscale[i]; ssh[i] = bnshift[i]; }
    }
    if (STATS && tid < 128) { ssum[tid] = 0.f; ssq[tid] = 0.f; }

    // ---- staging thread mapping ----
    const int arow = tid >> 1;            // 0..127
    const int acol = (tid & 1) * 16;      // 0 or 16
    const bool avalid = (row0 + arow) < M;
    const float* Ap = A + (size_t)(row0 + arow) * K + acol;

    const int brow = tid >> 3;            // 0..31
    const int bcol = (tid & 7) * 16;      // 0..112

    float acc[2][8][4];
    #pragma unroll
    for (int i = 0; i < 2; i++)
        #pragma unroll
        for (int j = 0; j < 8; j++)
            #pragma unroll
            for (int q = 0; q < 4; q++) acc[i][j][q] = 0.f;

    const uint32_t aHiB = smem_u32(sAhi);
    const uint32_t aLoB = smem_u32(sAlo);
    const uint32_t bB0  = smem_u32(sB[0]);
    const uint32_t bB1  = smem_u32(sB[1]);

    // lane-invariant fragment address parts
    const uint32_t aoff = (uint32_t)((lane & 15) * APAD + (lane >> 4) * 16);
    const uint32_t boff = (uint32_t)((((lane >> 3) & 1) * 8 + (lane & 7)) * BPAD + (lane >> 4) * 16);

    const int nchunk = K >> 5;
    const uint32_t bdst = (uint32_t)(brow * BPAD + bcol * 2);

    // issue B chunk 0 into buffer 0
    cp_async16(bB0 + bdst,      Bp + (size_t)brow * Nd + col0 + bcol);
    cp_async16(bB0 + bdst + 16, Bp + (size_t)brow * Nd + col0 + bcol + 8);
    cp_commit();

    // prefetch A chunk 0 into registers
    float4 aval[4];
    if (avalid) {
        #pragma unroll
        for (int q = 0; q < 4; q++) aval[q] = *(const float4*)(Ap + q * 4);
    } else {
        #pragma unroll
        for (int q = 0; q < 4; q++) aval[q] = make_float4(0.f, 0.f, 0.f, 0.f);
    }
    __syncthreads();   // covers ssc/ssh/ssum init too

    for (int c = 0; c < nchunk; c++) {
        // ---- store A (convert fp32 -> fp16 hi/lo) ----
        {
            const int kb = c * 32 + acol;
            char* ah = sAhi + arow * APAD + acol * 2;
            char* al = sAlo + arow * APAD + acol * 2;
            #pragma unroll
            for (int q = 0; q < 4; q++) {
                float4 v = aval[q];
                if (BNA) {
                    const int k = kb + q * 4;
                    v.x = fmaxf(fmaf(v.x, ssc[k + 0], ssh[k + 0]), 0.f);
                    v.y = fmaxf(fmaf(v.y, ssc[k + 1], ssh[k + 1]), 0.f);
                    v.z = fmaxf(fmaf(v.z, ssc[k + 2], ssh[k + 2]), 0.f);
                    v.w = fmaxf(fmaf(v.w, ssc[k + 3], ssh[k + 3]), 0.f);
                }
                float hx = __half2float(__float2half_rn(v.x));
                float hy = __half2float(__float2half_rn(v.y));
                float hz = __half2float(__float2half_rn(v.z));
                float hw = __half2float(__float2half_rn(v.w));
                uint2 hv, lv;
                hv.x = packh2(v.x, v.y);
                hv.y = packh2(v.z, v.w);
                lv.x = packh2(v.x - hx, v.y - hy);
                lv.y = packh2(v.z - hz, v.w - hw);
                *(uint2*)(ah + q * 8) = hv;
                *(uint2*)(al + q * 8) = lv;
            }
        }
        // ---- issue next B chunk into the other buffer ----
        if (c + 1 < nchunk) {
            const uint32_t nb = ((c + 1) & 1) ? bB1 : bB0;
            const __half* bp = Bp + (size_t)((c + 1) * 32 + brow) * Nd + col0 + bcol;
            cp_async16(nb + bdst, bp);
            cp_async16(nb + bdst + 16, bp + 8);
            cp_commit();
            cp_wait1();     // B chunk c has landed
        } else {
            cp_wait0();
        }
        __syncthreads();
        // ---- prefetch next A chunk into registers ----
        if (c + 1 < nchunk && avalid) {
            const float* ap = Ap + (c + 1) * 32;
            #pragma unroll
            for (int q = 0; q < 4; q++) aval[q] = *(const float4*)(ap + q * 4);
        }
        // ---- compute on buffer c&1 ----
        const uint32_t bBc = (c & 1) ? bB1 : bB0;
        #pragma unroll
        for (int kk = 0; kk < 2; kk++) {
            uint32_t af[2][4], bx[8][2];
            #pragma unroll
            for (int p = 0; p < 4; p++) {
                uint32_t r[4];
                ldsm4t(r, bBc + boff + (uint32_t)(kk * 16 * BPAD + (64 * wn + p * 16) * 2));
                bx[2 * p][0] = r[0]; bx[2 * p][1] = r[1];
                bx[2 * p + 1][0] = r[2]; bx[2 * p + 1][1] = r[3];
            }
            #pragma unroll
            for (int i = 0; i < 2; i++)
                ldsm4(af[i], aHiB + aoff + (uint32_t)((32 * wm + 16 * i) * APAD + kk * 32));
            #pragma unroll
            for (int i = 0; i < 2; i++)
                #pragma unroll
                for (int j = 0; j < 8; j++)
                    mma16816(acc[i][j], af[i], bx[j][0], bx[j][1]);
            #pragma unroll
            for (int i = 0; i < 2; i++)
                ldsm4(af[i], aLoB + aoff + (uint32_t)((32 * wm + 16 * i) * APAD + kk * 32));
            #pragma unroll
            for (int i = 0; i < 2; i++)
                #pragma unroll
                for (int j = 0; j < 8; j++)
                    mma16816(acc[i][j], af[i], bx[j][0], bx[j][1]);
        }
        if (c + 1 < nchunk) __syncthreads();   // A smem reusable next iter
    }

    // ---- epilogue ----
    const int m4 = lane >> 2;
    const int n2 = (lane & 3) * 2;

    float bcolv[16];
    #pragma unroll
    for (int j = 0; j < 8; j++) {
        if (bias) {
            float2 b2 = *(const float2*)(bias + col0 + 64 * wn + 8 * j + n2);
            bcolv[2 * j] = b2.x; bcolv[2 * j + 1] = b2.y;
        } else {
            bcolv[2 * j] = 0.f; bcolv[2 * j + 1] = 0.f;
        }
    }
    float csum[16], csq[16];
    if (STATS) {
        #pragma unroll
        for (int q = 0; q < 16; q++) { csum[q] = 0.f; csq[q] = 0.f; }
    }

    #pragma unroll
    for (int i = 0; i < 2; i++) {
        const int rb = row0 + 32 * wm + 16 * i + m4;
        #pragma unroll
        for (int hf = 0; hf < 2; hf++) {
            const int r = rb + 8 * hf;
            if (r >= M) continue;
            int si = 0, di = 0, gi2 = 0, sg = 0;
            if (GATH) { si = src[r]; di = dst[r]; gi2 = gid[si]; }
            if (SCAT) sg = seg[r];
            #pragma unroll
            for (int j = 0; j < 8; j++) {
                const int gc = col0 + 64 * wn + 8 * j + n2;
                float v0 = acc[i][j][2 * hf]     + bcolv[2 * j];
                float v1 = acc[i][j][2 * hf + 1] + bcolv[2 * j + 1];
                if (GATH) {
                    float2 g1 = *(const float2*)(Ph + (size_t)si * HID + gc);
                    float2 g2 = *(const float2*)(Ph + (size_t)di * HID + gc);
                    float2 g3 = *(const float2*)(U1 + (size_t)gi2 * HID + gc);
                    v0 += g1.x + g2.x + g3.x;
                    v1 += g1.y + g2.y + g3.y;
                }
                *(float2*)(C + (size_t)r * Nd + gc) = make_float2(v0, v1);
                if (SCAT) {
                    float* so = segout + (size_t)sg * Nd + gc;
                    atomicAdd(so, v0); atomicAdd(so + 1, v1);
                }
                if (STATS) {
                    csum[2 * j] += v0;     csq[2 * j] += v0 * v0;
                    csum[2 * j + 1] += v1; csq[2 * j + 1] += v1 * v1;
                }
            }
        }
    }
    if (STATS) {
        #pragma unroll
        for (int j = 0; j < 8; j++) {
            const int cl0 = 64 * wn + 8 * j + n2;
            atomicAdd(&ssum[cl0], csum[2 * j]);
            atomicAdd(&ssum[cl0 + 1], csum[2 * j + 1]);
            atomicAdd(&ssq[cl0], csq[2 * j]);
            atomicAdd(&ssq[cl0 + 1], csq[2 * j + 1]);
        }
        __syncthreads();
        if (tid < 128) {
            atomicAdd(&st_sum[col0 + tid], ssum[tid]);
            atomicAdd(&st_sq[col0 + tid], ssq[tid]);
        }
    }
}

// ---------------------------------------------------------------------------
// Elementwise / scatter kernels
// ---------------------------------------------------------------------------
__global__ void zerok(float* __restrict__ p, size_t n) {
    size_t i = (size_t)blockIdx.x * blockDim.x + threadIdx.x;
    size_t st = (size_t)gridDim.x * blockDim.x;
    for (; i < n; i += st) p[i] = 0.f;
}

__global__ void edge_scatter_h(const float* __restrict__ h, const int* __restrict__ src,
                               const int* __restrict__ dst, float* __restrict__ SH, int E)
{
    int idx = blockIdx.x * blockDim.x + threadIdx.x;
    int tot = E * 32;
    if (idx >= tot) return;
    int ei = idx >> 5;
    int c  = (idx & 31) << 2;
    int s = src[ei], d = dst[ei];
    float4 v = *(const float4*)&h[(size_t)s * D + c];
    float* o = SH + (size_t)d * D + c;
    atomicAdd(o + 0, v.x); atomicAdd(o + 1, v.y);
    atomicAdd(o + 2, v.z); atomicAdd(o + 3, v.w);
}

__global__ void bn_prep(float* __restrict__ sum, float* __restrict__ sq,
                        const float* __restrict__ g1, const float* __restrict__ beta1,
                        float* __restrict__ scale, float* __restrict__ shift, float invM)
{
    const int c = threadIdx.x;
    float mean = sum[c] * invM;
    float var  = sq[c] * invM - mean * mean;
    float rstd = rsqrtf(var + 1e-5f);
    float sc = rstd * g1[c];
    scale[c] = sc;
    shift[c] = beta1[c] - mean * sc;
    sum[c] = 0.f;
    sq[c] = 0.f;
}

__global__ void node_build(const float* __restrict__ h, const float* __restrict__ u,
                           const int* __restrict__ gid,
                           const float* __restrict__ SH, const float* __restrict__ SE,
                           float* __restrict__ Xa, float* __restrict__ UE, int N)
{
    int idx = blockIdx.x * blockDim.x + threadIdx.x;
    int tot = N * 32;
    if (idx >= tot) return;
    int n = idx >> 5;
    int c = (idx & 31) << 2;
    int g = gid[n];
    float4 sh = *(const float4*)&SH[(size_t)n * D + c];
    float4 hv = *(const float4*)&h[(size_t)n * D + c];
    float4 se = *(const float4*)&SE[(size_t)n * D + c];
    float4 uv = *(const float4*)&u[(size_t)g * D + c];
    size_t base = (size_t)n * HID;
    *(float4*)&Xa[base + c]         = make_float4(sh.x + hv.x, sh.y + hv.y, sh.z + hv.z, sh.w + hv.w);
    *(float4*)&Xa[base + D + c]     = se;
    *(float4*)&Xa[base + 2 * D + c] = uv;
    float* o = UE + (size_t)g * D + c;
    atomicAdd(o + 0, 0.5f * se.x); atomicAdd(o + 1, 0.5f * se.y);
    atomicAdd(o + 2, 0.5f * se.z); atomicAdd(o + 3, 0.5f * se.w);
}

__global__ void graph_build(const float* __restrict__ u, const float* __restrict__ UH,
                            const float* __restrict__ UE, float* __restrict__ Xg, int G)
{
    int idx = blockIdx.x * blockDim.x + threadIdx.x;
    int tot = G * 32;
    if (idx >= tot) return;
    int g = idx >> 5;
    int c = (idx & 31) << 2;
    size_t base = (size_t)g * HID;
    *(float4*)&Xg[base + c]         = *(const float4*)&UH[(size_t)g * D + c];
    *(float4*)&Xg[base + D + c]     = *(const float4*)&UE[(size_t)g * D + c];
    *(float4*)&Xg[base + 2 * D + c] = *(const float4*)&u[(size_t)g * D + c];
}

// ---------------------------------------------------------------------------
// Dispatch. mode: 0 plain, 1 GATH+STATS, 2 BNA+SCAT, 3 STATS, 4 BNA
// ---------------------------------------------------------------------------
static void run_gemm_mma(int mode,
                         const float* A, const __half* Bp, const float* bias, float* C,
                         int M, int K, int Nd,
                         const float* sc, const float* sh,
                         const int* seg, float* segout,
                         const float* Ph, const float* U1,
                         const int* src, const int* dst, const int* gid,
                         float* st_sum, float* st_sq)
{
    dim3 grid(Nd / 128, (M + 127) / 128);
    switch (mode) {
    case 0: gemm_mma<false,false,false,false><<<grid,256>>>(A,Bp,bias,C,M,K,Nd,sc,sh,seg,segout,Ph,U1,src,dst,gid,st_sum,st_sq); break;
    case 1: gemm_mma<false,false,true, true ><<<grid,256>>>(A,Bp,bias,C,M,K,Nd,sc,sh,seg,segout,Ph,U1,src,dst,gid,st_sum,st_sq); break;
    case 2: gemm_mma<true, true, false,false><<<grid,256>>>(A,Bp,bias,C,M,K,Nd,sc,sh,seg,segout,Ph,U1,src,dst,gid,st_sum,st_sq); break;
    case 3: gemm_mma<false,false,false,true ><<<grid,256>>>(A,Bp,bias,C,M,K,Nd,sc,sh,seg,segout,Ph,U1,src,dst,gid,st_sum,st_sq); break;
    case 4: gemm_mma<true, false,false,false><<<grid,256>>>(A,Bp,bias,C,M,K,Nd,sc,sh,seg,segout,Ph,U1,src,dst,gid,st_sum,st_sq); break;
    }
}

extern "C" void kernel_launch(void* const* d_in, const int* in_sizes, int n_in,
                              void* d_out, int out_size)
{
    const float* h   = (const float*)d_in[0];
    const float* e   = (const float*)d_in[1];
    const float* u   = (const float*)d_in[2];
    const int*   src = (const int*)d_in[3];
    const int*   dst = (const int*)d_in[4];
    const int*   gid = (const int*)d_in[5];

    const float* bW1 = (const float*)d_in[6];
    const float* bb1 = (const float*)d_in[7];
    const float* bg1 = (const float*)d_in[8];
    const float* bbt = (const float*)d_in[9];
    const float* bW2 = (const float*)d_in[10];
    const float* bb2 = (const float*)d_in[11];

    const float* aW1 = (const float*)d_in[12];
    const float* ab1 = (const float*)d_in[13];
    const float* ag1 = (const float*)d_in[14];
    const float* abt = (const float*)d_in[15];
    const float* aW2 = (const float*)d_in[16];
    const float* ab2 = (const float*)d_in[17];

    const float* gW1 = (const float*)d_in[18];
    const float* gb1 = (const float*)d_in[19];
    const float* gg1 = (const float*)d_in[20];
    const float* gbt = (const float*)d_in[21];
    const float* gW2 = (const float*)d_in[22];
    const float* gb2 = (const float*)d_in[23];

    const int N = in_sizes[5];
    const int E = in_sizes[3];
    const int G = in_sizes[2] / D;

    float* scratch = nullptr;
    cudaGetSymbolAddress((void**)&scratch, g_scratch);

    float* Zb = scratch + OFF_ZB;
    float* Ph = scratch + OFF_PH;
    float* U1 = scratch + OFF_U1;
    float* Xa = scratch + OFF_XA;
    float* Za = scratch + OFF_ZA;
    float* Xg = scratch + OFF_XG;
    float* Zg = scratch + OFF_ZG;
    float* SH = scratch + OFF_SH;
    float* SE = scratch + OFF_SE;
    float* UH = scratch + OFF_UH;
    float* UE = scratch + OFF_UE;
    float* st_sum   = scratch + OFF_ST;
    float* st_sq    = st_sum + HID;
    float* bn_scale = st_sq + HID;
    float* bn_shift = bn_scale + HID;
    __half* WP = (__half*)(scratch + OFF_WP);

    float* out_h = (float*)d_out;
    float* out_e = out_h + (size_t)N * D;
    float* out_u = out_e + (size_t)E * D;

    // Zero accumulators (SH, SE, UH, UE, stats) — contiguous region.
    {
        size_t nz = (size_t)MAXN * D * 2 + (size_t)MAXG * D * 2 + 2 * HID;
        zerok<<<2048, 256>>>(SH, nz);
    }

    // Pre-convert all weights to dense fp16.
    {
        const int T1 = 128 * HID, T2 = HID * HID, T3 = HID * D;
        prep_weight<<<(T1 + 255) / 256, 256>>>(bW1,                       WP + WPO_BW1A, T1);
        prep_weight<<<(T1 + 255) / 256, 256>>>(bW1 + (size_t)D * HID,     WP + WPO_BW1B, T1);
        prep_weight<<<(T1 + 255) / 256, 256>>>(bW1 + (size_t)2 * D * HID, WP + WPO_BW1C, T1);
        prep_weight<<<(T3 + 255) / 256, 256>>>(bW2, WP + WPO_BW2, T3);
        prep_weight<<<(T2 + 255) / 256, 256>>>(aW1, WP + WPO_AW1, T2);
        prep_weight<<<(T3 + 255) / 256, 256>>>(aW2, WP + WPO_AW2, T3);
        prep_weight<<<(T2 + 255) / 256, 256>>>(gW1, WP + WPO_GW1, T2);
        prep_weight<<<(T3 + 255) / 256, 256>>>(gW2, WP + WPO_GW2, T3);
    }

    // ---- Bond path ----
    run_gemm_mma(0, h, WP + WPO_BW1A, nullptr, Ph, N, 128, HID,
                 nullptr, nullptr, nullptr, nullptr, nullptr, nullptr, nullptr, nullptr, nullptr, nullptr, nullptr);
    run_gemm_mma(0, u, WP + WPO_BW1C, bb1, U1, G, 128, HID,
                 nullptr, nullptr, nullptr, nullptr, nullptr, nullptr, nullptr, nullptr, nullptr, nullptr, nullptr);
    edge_scatter_h<<<(E * 32 + 255) / 256, 256>>>(h, src, dst, SH, E);
    // Zb = e@bW1b + Ph[src] + Ph[dst] + U1[gid[src]]; fused stats
    run_gemm_mma(1, e, WP + WPO_BW1B, nullptr, Zb, E, 128, HID,
                 nullptr, nullptr, nullptr, nullptr, Ph, U1, src, dst, gid, st_sum, st_sq);
    bn_prep<<<1, HID>>>(st_sum, st_sq, bg1, bbt, bn_scale, bn_shift, 1.f / (float)E);
    // e_new = relu(BN(Zb)) @ bW2 + bb2 ; SE[dst] += e_new
    run_gemm_mma(2, Zb, WP + WPO_BW2, bb2, out_e, E, HID, D,
                 bn_scale, bn_shift, dst, SE, nullptr, nullptr, nullptr, nullptr, nullptr, nullptr, nullptr);

    // ---- Atom path ----
    node_build<<<(N * 32 + 255) / 256, 256>>>(h, u, gid, SH, SE, Xa, UE, N);
    run_gemm_mma(3, Xa, WP + WPO_AW1, ab1, Za, N, HID, HID,
                 nullptr, nullptr, nullptr, nullptr, nullptr, nullptr, nullptr, nullptr, nullptr, st_sum, st_sq);
    bn_prep<<<1, HID>>>(st_sum, st_sq, ag1, abt, bn_scale, bn_shift, 1.f / (float)N);
    run_gemm_mma(2, Za, WP + WPO_AW2, ab2, out_h, N, HID, D,
                 bn_scale, bn_shift, gid, UH, nullptr, nullptr, nullptr, nullptr, nullptr, nullptr, nullptr);

    // ---- Global path ----
    graph_build<<<(G * 32 + 255) / 256, 256>>>(u, UH, UE, Xg, G);
    run_gemm_mma(3, Xg, WP + WPO_GW1, gb1, Zg, G, HID, HID,
                 nullptr, nullptr, nullptr, nullptr, nullptr, nullptr, nullptr, nullptr, nullptr, st_sum, st_sq);
    bn_prep<<<1, HID>>>(st_sum, st_sq, gg1, gbt, bn_scale, bn_shift, 1.f / (float)G);
    run_gemm_mma(4, Zg, WP + WPO_GW2, gb2, out_u, G, HID, D,
                 bn_scale, bn_shift, nullptr, nullptr, nullptr, nullptr, nullptr, nullptr, nullptr, nullptr, nullptr);
}